// round 10
// baseline (speedup 1.0000x reference)
#include <cuda_runtime.h>
#include <cuda_bf16.h>
#include <cstdint>
#include <cstddef>

#define TPB 224
#define NWARP 7

typedef unsigned long long ull;

// C context: [col/4][elem] float4 (intermediate), and fragment-packed per warp.
__device__ float4 g_C[32 * 32768];
__device__ float4 g_Cf[1056 * 32 * 32];   // [gwarp][mt*16+nt][lane]

// ---------------- packed f32x2 ----------------
__device__ __forceinline__ ull ffma2(ull a, ull b, ull c) {
    ull d; asm("fma.rn.f32x2 %0, %1, %2, %3;" : "=l"(d) : "l"(a), "l"(b), "l"(c)); return d;
}
__device__ __forceinline__ ull pack2(float lo, float hi) {
    ull r; asm("mov.b64 %0, {%1, %2};" : "=l"(r) : "f"(lo), "f"(hi)); return r;
}
__device__ __forceinline__ void unpack2(ull v, float& lo, float& hi) {
    asm("mov.b64 {%0, %1}, %2;" : "=f"(lo), "=f"(hi) : "l"(v));
}
__device__ __forceinline__ uint32_t bf16x2_of(float lo, float hi) {
    uint32_t r; asm("cvt.rn.bf16x2.f32 %0, %1, %2;" : "=r"(r) : "f"(hi), "f"(lo)); return r;
}
__device__ __forceinline__ float tanh_hw(float x) {
    float y; asm("tanh.approx.f32 %0, %1;" : "=f"(y) : "f"(x)); return y;
}
__device__ __forceinline__ float softplus_(float x) {
    return fmaxf(x, 0.0f) + __logf(1.0f + __expf(-fabsf(x)));
}
__device__ __forceinline__ void mma16816(float* c, const uint32_t* a, uint32_t b0, uint32_t b1) {
    asm volatile("mma.sync.aligned.m16n8k16.row.col.f32.bf16.bf16.f32 "
        "{%0,%1,%2,%3}, {%4,%5,%6,%7}, {%8,%9}, {%0,%1,%2,%3};"
        : "+f"(c[0]), "+f"(c[1]), "+f"(c[2]), "+f"(c[3])
        : "r"(a[0]), "r"(a[1]), "r"(a[2]), "r"(a[3]), "r"(b0), "r"(b1));
}
__device__ __forceinline__ void ldm_x4(uint32_t* r, uint32_t addr) {
    asm volatile("ldmatrix.sync.aligned.m8n8.x4.shared.b16 {%0,%1,%2,%3}, [%4];"
        : "=r"(r[0]), "=r"(r[1]), "=r"(r[2]), "=r"(r[3]) : "r"(addr));
}
__device__ __forceinline__ uint32_t smem_u32(const void* p) {
    uint32_t a;
    asm("{ .reg .u64 t; cvta.to.shared.u64 t, %1; cvt.u32.u64 %0, t; }" : "=r"(a) : "l"(p));
    return a;
}

// ---------------- SMEM byte layout ----------------
#define ZBUF_BYTE  0                       // 7 warps x 32 rows x 80B
#define W1T_BYTE   17920                   // 128 n-rows x 80B (32 bf16 k: hi|lo|hi|0)
#define ROUTE_BYTE 28160                   // 7 x 32 x 48B
#define DB2_BYTE   38912                   // 128 f
#define WT_BYTE    39424                   // 128 f (t-row of dW1, fp32)
#define W3P_BYTE   39936                   // [128][12] f
#define GW1_BYTE   46080                   // [32][12] f
#define GW2_BYTE   47616                   // [32][12] f
#define GB1_BYTE   49152                   // 32 f
#define TS_BYTE    49280                   // 128 f
#define GB2_BYTE   49792                   // 16 f
#define DB3_BYTE   49856                   // 16 f
#define BHI_BYTE   49920                   // W2^T hi: 128 x 272B
#define BLO_BYTE   84736                   // W2^T lo
#define SMEM_BYTES 119552

__global__ void __launch_bounds__(TPB, 1)
sde_hmma(const float* __restrict__ z0, const float* __restrict__ activity,
         const float* __restrict__ rest, const float* __restrict__ ts,
         const float* __restrict__ noise,
         const float* __restrict__ aW1, const float* __restrict__ ab1,
         const float* __restrict__ aW2, const float* __restrict__ ab2,
         const float* __restrict__ rW1, const float* __restrict__ rb1,
         const float* __restrict__ rW2, const float* __restrict__ rb2,
         const float* __restrict__ dW1, const float* __restrict__ db1,
         const float* __restrict__ dW2, const float* __restrict__ db2,
         const float* __restrict__ dW3, const float* __restrict__ db3,
         const float* __restrict__ gW1, const float* __restrict__ gb1,
         const float* __restrict__ gW2, const float* __restrict__ gb2,
         float* __restrict__ out, int Bn, int nstep)
{
    extern __shared__ char smc[];
    const uint32_t sbase = smem_u32(smc);
    const int tid  = threadIdx.x;
    const int wid  = tid >> 5;
    const int lane = tid & 31;
    const int gid  = lane >> 2;
    const int tid4 = lane & 3;
    const int qc   = tid4 * 2;
    const int elem = blockIdx.x * TPB + tid;
    const int elemBase = blockIdx.x * TPB + wid * 32;
    const bool active = (elemBase < Bn);            // warp-uniform (Bn % 32 == 0)
    const int gw = blockIdx.x * NWARP + wid;

    // ================= one-time staging =================
    // W2^T hi/lo bf16: BT[n][k] at n*272 + 2k
    for (int i = tid; i < 16384; i += TPB) {
        int k = i >> 7, n = i & 127;
        float w = dW2[i];
        __nv_bfloat16 hi = __float2bfloat16(w);
        __nv_bfloat16 lo = __float2bfloat16(w - __bfloat162float(hi));
        uint32_t off = (uint32_t)n * 272u + (uint32_t)k * 2u;
        *(__nv_bfloat16*)(smc + BHI_BYTE + off) = hi;
        *(__nv_bfloat16*)(smc + BLO_BYTE + off) = lo;
    }
    if (tid < 128) {
        // W1T row n=tid: k0..9 = hi(dW1[j][n]), k10..19 = lo, k20..29 = hi, rest 0
        __nv_bfloat16* r = (__nv_bfloat16*)(smc + W1T_BYTE + tid * 80);
        #pragma unroll
        for (int k = 0; k < 40; ++k) r[k] = __float2bfloat16(0.0f);
        #pragma unroll
        for (int j = 0; j < 10; ++j) {
            float w = dW1[j * 128 + tid];
            __nv_bfloat16 hi = __float2bfloat16(w);
            __nv_bfloat16 lo = __float2bfloat16(w - __bfloat162float(hi));
            r[j] = hi; r[10 + j] = lo; r[20 + j] = hi;
        }
        ((float*)(smc + WT_BYTE))[tid]  = dW1[106 * 128 + tid];
        ((float*)(smc + DB2_BYTE))[tid] = db2[tid];
        float* w3r = (float*)(smc + W3P_BYTE + tid * 48);
        #pragma unroll
        for (int j = 0; j < 10; ++j) w3r[j] = dW3[tid * 10 + j];
        w3r[10] = 0.0f; w3r[11] = 0.0f;
    }
    if (tid < 32) {
        float* g1r = (float*)(smc + GW1_BYTE + tid * 48);
        #pragma unroll
        for (int j = 0; j < 10; ++j) g1r[j] = gW1[j * 32 + tid];
        g1r[10] = gW1[10 * 32 + tid];
        g1r[11] = 0.0f;
        float* g2r = (float*)(smc + GW2_BYTE + tid * 48);
        #pragma unroll
        for (int j = 0; j < 10; ++j) g2r[j] = gW2[tid * 10 + j];
        g2r[10] = 0.0f; g2r[11] = 0.0f;
        ((float*)(smc + GB1_BYTE))[tid] = gb1[tid];
    }
    if (tid < 16) {
        ((float*)(smc + GB2_BYTE))[tid] = (tid < 10) ? gb2[tid] : 0.0f;
        ((float*)(smc + DB3_BYTE))[tid] = (tid < 10) ? db3[tid] : 0.0f;
    }
    for (int i = tid; i <= nstep && i < 128; i += TPB)
        ((float*)(smc + TS_BYTE))[i] = ts[i];

    // ---- context encoders -> C[128] -> g_C [col4][elem] ----
    if (elem < Bn) {
        float actv[6], rsv[3];
        #pragma unroll
        for (int j = 0; j < 6; ++j) actv[j] = activity[elem * 6 + j];
        #pragma unroll
        for (int j = 0; j < 3; ++j) rsv[j] = rest[elem * 3 + j];
        float ha[32];
        #pragma unroll
        for (int o = 0; o < 32; ++o) {
            float q = __ldg(&ab1[o]);
            #pragma unroll
            for (int j = 0; j < 6; ++j) q += actv[j] * __ldg(&aW1[j * 32 + o]);
            ha[o] = fmaxf(q, 0.0f);
        }
        float av[64];
        #pragma unroll
        for (int o = 0; o < 64; ++o) {
            float q = __ldg(&ab2[o]);
            #pragma unroll
            for (int j = 0; j < 32; ++j) q += ha[j] * __ldg(&aW2[j * 64 + o]);
            av[o] = q;
        }
        float hr[16];
        #pragma unroll
        for (int o = 0; o < 16; ++o) {
            float q = __ldg(&rb1[o]);
            #pragma unroll
            for (int j = 0; j < 3; ++j) q += rsv[j] * __ldg(&rW1[j * 16 + o]);
            hr[o] = fmaxf(q, 0.0f);
        }
        float rv[32];
        #pragma unroll
        for (int o = 0; o < 32; ++o) {
            float q = __ldg(&rb2[o]);
            #pragma unroll
            for (int j = 0; j < 16; ++j) q += hr[j] * __ldg(&rW2[j * 32 + o]);
            rv[o] = q;
        }
        for (int o4 = 0; o4 < 32; ++o4) {
            float cv[4];
            #pragma unroll
            for (int c = 0; c < 4; ++c) {
                int o = o4 * 4 + c;
                float q = __ldg(&db1[o]);
                #pragma unroll
                for (int j = 0; j < 64; ++j) q += av[j] * __ldg(&dW1[(10 + j) * 128 + o]);
                #pragma unroll
                for (int j = 0; j < 32; ++j) q += rv[j] * __ldg(&dW1[(74 + j) * 128 + o]);
                cv[c] = q;
            }
            g_C[(size_t)o4 * Bn + elem] = make_float4(cv[0], cv[1], cv[2], cv[3]);
        }
    }
    __syncthreads();   // g_C visible CTA-wide; smem staged

    float z[10];
    if (active) {
        // ---- repack C into fragment layout g_Cf ----
        #pragma unroll
        for (int mt = 0; mt < 2; ++mt)
            for (int nt = 0; nt < 16; ++nt) {
                int R0 = elemBase + mt * 16 + gid;
                int o4 = 2 * nt + (tid4 >> 1);
                float4 v0 = g_C[(size_t)o4 * Bn + R0];
                float4 v1 = g_C[(size_t)o4 * Bn + R0 + 8];
                float4 fr;
                if (tid4 & 1) { fr.x = v0.z; fr.y = v0.w; fr.z = v1.z; fr.w = v1.w; }
                else          { fr.x = v0.x; fr.y = v0.y; fr.z = v1.x; fr.w = v1.y; }
                g_Cf[((size_t)gw * 32 + mt * 16 + nt) * 32 + lane] = fr;
            }
        // z0 + output row 0
        #pragma unroll
        for (int j = 0; j < 10; ++j) z[j] = z0[elem * 10 + j];
        float2* op0 = (float2*)(out + (size_t)elem * 10);
        #pragma unroll
        for (int j = 0; j < 5; ++j) op0[j] = make_float2(z[2 * j], z[2 * j + 1]);
    }
    if (!active) return;    // no further __syncthreads

    // precomputed addresses
    const uint32_t zwarp = sbase + ZBUF_BYTE + (uint32_t)wid * (32 * 80);
    const uint32_t zaL   = zwarp + (uint32_t)(lane & 15) * 80u + ((uint32_t)(lane >> 4) & 1u) * 16u;
    const uint32_t w1L   = sbase + W1T_BYTE + (uint32_t)(lane & 7) * 80u
                         + (((uint32_t)lane >> 3) & 1u) * 16u + (((uint32_t)lane >> 4) & 1u) * 640u;
    const uint32_t bLdmLane = (uint32_t)(lane & 7) * 272u + ((uint32_t)lane >> 3) * 16u;
    float* route = (float*)(smc + ROUTE_BYTE + wid * 32 * 48);
    const float* tsf = (const float*)(smc + TS_BYTE);
    const float4* cfp = &g_Cf[(size_t)gw * 32 * 32 + lane];

    // ================= SDE integration (warp-synchronous) =================
    for (int s = 0; s < nstep; ++s) {
        const float t  = tsf[s];
        const float dt = tsf[s + 1] - t;
        const float sq = sqrtf(dt);

        // ---- z-aug row: [z_hi | z_hi | z_lo | 0] as 16 bf16x2 ----
        {
            unsigned short hs[10]; float zl[10];
            #pragma unroll
            for (int j = 0; j < 10; ++j) {
                __nv_bfloat16 h = __float2bfloat16(z[j]);
                hs[j] = __bfloat16_as_ushort(h);
                zl[j] = z[j] - __bfloat162float(h);
            }
            uint32_t p[16];
            #pragma unroll
            for (int i = 0; i < 5; ++i) {
                p[i] = (uint32_t)hs[2 * i] | ((uint32_t)hs[2 * i + 1] << 16);
                p[5 + i] = p[i];
                p[10 + i] = bf16x2_of(zl[2 * i], zl[2 * i + 1]);
            }
            p[15] = 0u;
            uint32_t dst = zwarp + (uint32_t)lane * 80u;
            asm volatile("st.shared.v4.b32 [%0], {%1,%2,%3,%4};" :: "r"(dst),
                "r"(p[0]), "r"(p[1]), "r"(p[2]), "r"(p[3]));
            asm volatile("st.shared.v4.b32 [%0], {%1,%2,%3,%4};" :: "r"(dst + 16),
                "r"(p[4]), "r"(p[5]), "r"(p[6]), "r"(p[7]));
            asm volatile("st.shared.v4.b32 [%0], {%1,%2,%3,%4};" :: "r"(dst + 32),
                "r"(p[8]), "r"(p[9]), "r"(p[10]), "r"(p[11]));
            asm volatile("st.shared.v4.b32 [%0], {%1,%2,%3,%4};" :: "r"(dst + 48),
                "r"(p[12]), "r"(p[13]), "r"(p[14]), "r"(p[15]));
        }
        __syncwarp();

        uint32_t za[2][2][4];
        #pragma unroll
        for (int mt = 0; mt < 2; ++mt)
            #pragma unroll
            for (int ks = 0; ks < 2; ++ks)
                ldm_x4(za[mt][ks], zaL + (uint32_t)mt * 1280u + (uint32_t)ks * 32u);

        // ---- GEMM1: h1 = tanh(zaug @ W1T + C + t*wt) -> A-frags in registers ----
        uint32_t af[2][8][4];
        #pragma unroll
        for (int mt = 0; mt < 2; ++mt) {
            float a1[16][4];
            #pragma unroll
            for (int nt = 0; nt < 16; ++nt) {
                float4 cf = __ldg(cfp + (mt * 16 + nt) * 32);
                float2 w2 = *(const float2*)(smc + WT_BYTE + (nt * 8 + qc) * 4);
                a1[nt][0] = fmaf(t, w2.x, cf.x);
                a1[nt][1] = fmaf(t, w2.y, cf.y);
                a1[nt][2] = fmaf(t, w2.x, cf.z);
                a1[nt][3] = fmaf(t, w2.y, cf.w);
            }
            #pragma unroll
            for (int ks = 0; ks < 2; ++ks)
                #pragma unroll
                for (int i = 0; i < 8; ++i) {
                    uint32_t bw[4];
                    ldm_x4(bw, w1L + (uint32_t)i * 1280u + (uint32_t)ks * 32u);
                    mma16816(a1[2 * i],     za[mt][ks], bw[0], bw[1]);
                    mma16816(a1[2 * i + 1], za[mt][ks], bw[2], bw[3]);
                }
            #pragma unroll
            for (int kt = 0; kt < 8; ++kt) {
                af[mt][kt][0] = bf16x2_of(tanh_hw(a1[2 * kt][0]),     tanh_hw(a1[2 * kt][1]));
                af[mt][kt][1] = bf16x2_of(tanh_hw(a1[2 * kt][2]),     tanh_hw(a1[2 * kt][3]));
                af[mt][kt][2] = bf16x2_of(tanh_hw(a1[2 * kt + 1][0]), tanh_hw(a1[2 * kt + 1][1]));
                af[mt][kt][3] = bf16x2_of(tanh_hw(a1[2 * kt + 1][2]), tanh_hw(a1[2 * kt + 1][3]));
            }
        }

        // ---- GEMM2 (hi+lo) + scalar epilogue ----
        ull dzp[4][5];
        #pragma unroll
        for (int ss = 0; ss < 4; ++ss)
            #pragma unroll
            for (int jj = 0; jj < 5; ++jj) dzp[ss][jj] = pack2(0.0f, 0.0f);

        #pragma unroll
        for (int ng = 0; ng < 4; ++ng) {
            float acc[2][4][4];
            #pragma unroll
            for (int ni = 0; ni < 4; ++ni) {
                float2 d2 = *(const float2*)(smc + DB2_BYTE + ((ng * 4 + ni) * 8 + qc) * 4);
                #pragma unroll
                for (int mt = 0; mt < 2; ++mt) {
                    acc[mt][ni][0] = d2.x; acc[mt][ni][1] = d2.y;
                    acc[mt][ni][2] = d2.x; acc[mt][ni][3] = d2.y;
                }
            }
            #pragma unroll
            for (int pass = 0; pass < 2; ++pass) {
                const uint32_t bb = sbase + (pass ? BLO_BYTE : BHI_BYTE) + bLdmLane;
                #pragma unroll
                for (int ni = 0; ni < 4; ++ni) {
                    const uint32_t brow = bb + (uint32_t)((ng * 4 + ni) * 8) * 272u;
                    #pragma unroll
                    for (int ktp = 0; ktp < 4; ++ktp) {
                        uint32_t r[4];
                        ldm_x4(r, brow + (uint32_t)ktp * 64u);
                        mma16816(acc[0][ni], af[0][2 * ktp],     r[0], r[1]);
                        mma16816(acc[1][ni], af[1][2 * ktp],     r[0], r[1]);
                        mma16816(acc[0][ni], af[0][2 * ktp + 1], r[2], r[3]);
                        mma16816(acc[1][ni], af[1][2 * ktp + 1], r[2], r[3]);
                    }
                }
            }
            #pragma unroll
            for (int ni = 0; ni < 4; ++ni) {
                const int cb = (ng * 4 + ni) * 8 + qc;
                const ull* w3a = (const ull*)(smc + W3P_BYTE + cb * 48);
                const ull* w3b = (const ull*)(smc + W3P_BYTE + (cb + 1) * 48);
                ull wa[5], wb[5];
                #pragma unroll
                for (int jj = 0; jj < 5; ++jj) { wa[jj] = w3a[jj]; wb[jj] = w3b[jj]; }
                #pragma unroll
                for (int mt = 0; mt < 2; ++mt) {
                    float h0 = tanh_hw(acc[mt][ni][0]);
                    float h1 = tanh_hw(acc[mt][ni][1]);
                    float h2 = tanh_hw(acc[mt][ni][2]);
                    float h3 = tanh_hw(acc[mt][ni][3]);
                    ull p0 = pack2(h0, h0), p1 = pack2(h1, h1);
                    ull p2 = pack2(h2, h2), p3 = pack2(h3, h3);
                    #pragma unroll
                    for (int jj = 0; jj < 5; ++jj) {
                        dzp[mt * 2][jj]     = ffma2(p0, wa[jj], dzp[mt * 2][jj]);
                        dzp[mt * 2][jj]     = ffma2(p1, wb[jj], dzp[mt * 2][jj]);
                        dzp[mt * 2 + 1][jj] = ffma2(p2, wa[jj], dzp[mt * 2 + 1][jj]);
                        dzp[mt * 2 + 1][jj] = ffma2(p3, wb[jj], dzp[mt * 2 + 1][jj]);
                    }
                }
            }
        }

        // ---- quad reduce + route dz to owner lane ----
        float dzf[4][10];
        #pragma unroll
        for (int ss = 0; ss < 4; ++ss)
            #pragma unroll
            for (int jj = 0; jj < 5; ++jj)
                unpack2(dzp[ss][jj], dzf[ss][2 * jj], dzf[ss][2 * jj + 1]);
        #pragma unroll
        for (int ss = 0; ss < 4; ++ss)
            #pragma unroll
            for (int j = 0; j < 10; ++j) {
                float v = dzf[ss][j];
                v += __shfl_xor_sync(0xffffffffu, v, 1);
                v += __shfl_xor_sync(0xffffffffu, v, 2);
                dzf[ss][j] = v;
            }
        if (tid4 == 0) {
            #pragma unroll
            for (int ss = 0; ss < 4; ++ss) {
                const int row = ((ss >> 1) << 4) + ((ss & 1) << 3) + gid;
                float2* rp = (float2*)(route + row * 12);
                #pragma unroll
                for (int jj = 0; jj < 5; ++jj)
                    rp[jj] = make_float2(dzf[ss][2 * jj], dzf[ss][2 * jj + 1]);
            }
        }
        __syncwarp();
        float dz[10];
        {
            const float* rp = route + lane * 12;
            const float* d3 = (const float*)(smc + DB3_BYTE);
            #pragma unroll
            for (int j = 0; j < 10; ++j) dz[j] = rp[j] + d3[j];
        }
        __syncwarp();

        // ---- diffusion MLP 11 -> 32 -> 10 ----
        ull zp[5];
        #pragma unroll
        for (int j = 0; j < 5; ++j) zp[j] = pack2(z[2 * j], z[2 * j + 1]);
        ull gvp[5];
        {
            const float2* g2 = (const float2*)(smc + GB2_BYTE);
            #pragma unroll
            for (int jj = 0; jj < 5; ++jj) gvp[jj] = pack2(g2[jj].x, g2[jj].y);
        }
        const float* gb1f = (const float*)(smc + GB1_BYTE);
        #pragma unroll 4
        for (int o = 0; o < 32; ++o) {
            const float4* g1 = (const float4*)(smc + GW1_BYTE + o * 48);
            float4 w0 = g1[0], w4 = g1[1], w8 = g1[2];
            ull p2 = pack2(gb1f[o], t * w8.z);
            p2 = ffma2(zp[0], pack2(w0.x, w0.y), p2);
            p2 = ffma2(zp[1], pack2(w0.z, w0.w), p2);
            p2 = ffma2(zp[2], pack2(w4.x, w4.y), p2);
            p2 = ffma2(zp[3], pack2(w4.z, w4.w), p2);
            p2 = ffma2(zp[4], pack2(w8.x, w8.y), p2);
            float plo, phi; unpack2(p2, plo, phi);
            float q = softplus_(plo + phi);
            ull qq = pack2(q, q);
            const ull* g2w = (const ull*)(smc + GW2_BYTE + o * 48);
            #pragma unroll
            for (int jj = 0; jj < 5; ++jj) gvp[jj] = ffma2(qq, g2w[jj], gvp[jj]);
        }

        // ---- Euler-Maruyama update + stream out ----
        const float2* np = (const float2*)(noise + ((size_t)s * Bn + elem) * 10);
        float2*       op = (float2*)(out + ((size_t)(s + 1) * Bn + elem) * 10);
        #pragma unroll
        for (int j = 0; j < 5; ++j) {
            float glo, ghi; unpack2(gvp[j], glo, ghi);
            float2 e = np[j];
            z[2 * j]     += dz[2 * j]     * dt + glo * sq * e.x;
            z[2 * j + 1] += dz[2 * j + 1] * dt + ghi * sq * e.y;
            op[j] = make_float2(z[2 * j], z[2 * j + 1]);
        }
    }
}

extern "C" void kernel_launch(void* const* d_in, const int* in_sizes, int n_in,
                              void* d_out, int out_size) {
    const float* z0       = (const float*)d_in[0];
    const float* activity = (const float*)d_in[1];
    const float* rest     = (const float*)d_in[2];
    const float* ts       = (const float*)d_in[3];
    const float* noise    = (const float*)d_in[4];
    const float* aW1 = (const float*)d_in[5];
    const float* ab1 = (const float*)d_in[6];
    const float* aW2 = (const float*)d_in[7];
    const float* ab2 = (const float*)d_in[8];
    const float* rW1 = (const float*)d_in[9];
    const float* rb1 = (const float*)d_in[10];
    const float* rW2 = (const float*)d_in[11];
    const float* rb2 = (const float*)d_in[12];
    const float* dW1 = (const float*)d_in[13];
    const float* db1 = (const float*)d_in[14];
    const float* dW2 = (const float*)d_in[15];
    const float* db2 = (const float*)d_in[16];
    const float* dW3 = (const float*)d_in[17];
    const float* db3 = (const float*)d_in[18];
    const float* gW1 = (const float*)d_in[19];
    const float* gb1 = (const float*)d_in[20];
    const float* gW2 = (const float*)d_in[21];
    const float* gb2 = (const float*)d_in[22];

    int B     = in_sizes[0] / 10;
    int nstep = in_sizes[3] - 1;

    cudaFuncSetAttribute(sde_hmma, cudaFuncAttributeMaxDynamicSharedMemorySize,
                         SMEM_BYTES);
    int grid = (B + TPB - 1) / TPB;
    sde_hmma<<<grid, TPB, SMEM_BYTES>>>(
        z0, activity, rest, ts, noise,
        aW1, ab1, aW2, ab2, rW1, rb1, rW2, rb2,
        dW1, db1, dW2, db2, dW3, db3,
        gW1, gb1, gW2, gb2,
        (float*)d_out, B, nstep);
}

// round 11
// speedup vs baseline: 1.0039x; 1.0039x over previous
#include <cuda_runtime.h>
#include <cuda_bf16.h>
#include <cuda_fp16.h>
#include <cstdint>
#include <cstddef>

#define TPB 448
#define NWARP 14
#define EPC 224          // elements per CTA (14 warps x 16)

typedef unsigned long long ull;

// C context: [col/4][elem] float4 (intermediate), and fragment-packed per warp.
__device__ float4 g_C[32 * 32768];
__device__ float4 g_Cf[2058 * 16 * 32];   // [gwarp][nt][lane]

// ---------------- packed f32x2 ----------------
__device__ __forceinline__ ull ffma2(ull a, ull b, ull c) {
    ull d; asm("fma.rn.f32x2 %0, %1, %2, %3;" : "=l"(d) : "l"(a), "l"(b), "l"(c)); return d;
}
__device__ __forceinline__ ull pack2(float lo, float hi) {
    ull r; asm("mov.b64 %0, {%1, %2};" : "=l"(r) : "f"(lo), "f"(hi)); return r;
}
__device__ __forceinline__ void unpack2(ull v, float& lo, float& hi) {
    asm("mov.b64 {%0, %1}, %2;" : "=f"(lo), "=f"(hi) : "l"(v));
}
__device__ __forceinline__ uint32_t bf16x2_of(float lo, float hi) {
    uint32_t r; asm("cvt.rn.bf16x2.f32 %0, %1, %2;" : "=r"(r) : "f"(hi), "f"(lo)); return r;
}
__device__ __forceinline__ uint32_t f16x2_of(float lo, float hi) {
    uint32_t r; asm("cvt.rn.f16x2.f32 %0, %1, %2;" : "=r"(r) : "f"(hi), "f"(lo)); return r;
}
__device__ __forceinline__ float tanh_hw(float x) {
    float y; asm("tanh.approx.f32 %0, %1;" : "=f"(y) : "f"(x)); return y;
}
__device__ __forceinline__ float softplus_(float x) {
    return fmaxf(x, 0.0f) + __logf(1.0f + __expf(-fabsf(x)));
}
// bf16 mma (GEMM1, exact hi/lo split path)
__device__ __forceinline__ void mma_bf16(float* c, const uint32_t* a, uint32_t b0, uint32_t b1) {
    asm volatile("mma.sync.aligned.m16n8k16.row.col.f32.bf16.bf16.f32 "
        "{%0,%1,%2,%3}, {%4,%5,%6,%7}, {%8,%9}, {%0,%1,%2,%3};"
        : "+f"(c[0]), "+f"(c[1]), "+f"(c[2]), "+f"(c[3])
        : "r"(a[0]), "r"(a[1]), "r"(a[2]), "r"(a[3]), "r"(b0), "r"(b1));
}
// fp16 mma (GEMM2, single pass)
__device__ __forceinline__ void mma_f16(float* c, const uint32_t* a, uint32_t b0, uint32_t b1) {
    asm volatile("mma.sync.aligned.m16n8k16.row.col.f32.f16.f16.f32 "
        "{%0,%1,%2,%3}, {%4,%5,%6,%7}, {%8,%9}, {%0,%1,%2,%3};"
        : "+f"(c[0]), "+f"(c[1]), "+f"(c[2]), "+f"(c[3])
        : "r"(a[0]), "r"(a[1]), "r"(a[2]), "r"(a[3]), "r"(b0), "r"(b1));
}
__device__ __forceinline__ void ldm_x4(uint32_t* r, uint32_t addr) {
    asm volatile("ldmatrix.sync.aligned.m8n8.x4.shared.b16 {%0,%1,%2,%3}, [%4];"
        : "=r"(r[0]), "=r"(r[1]), "=r"(r[2]), "=r"(r[3]) : "r"(addr));
}
__device__ __forceinline__ uint32_t smem_u32(const void* p) {
    uint32_t a;
    asm("{ .reg .u64 t; cvta.to.shared.u64 t, %1; cvt.u32.u64 %0, t; }" : "=r"(a) : "l"(p));
    return a;
}

// ---------------- SMEM byte layout ----------------
#define ZBUF_BYTE  0                       // 14 warps x 16 rows x 80B
#define W1T_BYTE   17920                   // 128 n-rows x 80B (bf16: hi|lo|hi|0)
#define ROUTE_BYTE 28160                   // 14 x 16 x 48B
#define DB2_BYTE   38912                   // 128 f
#define WT_BYTE    39424                   // 128 f (t-row of dW1, fp32)
#define W3P_BYTE   39936                   // [128][12] f
#define GW1_BYTE   46080                   // [32][12] f
#define GW2_BYTE   47616                   // [32][12] f
#define GB1_BYTE   49152                   // 32 f
#define TS_BYTE    49280                   // 128 f
#define GB2_BYTE   49792                   // 16 f
#define DB3_BYTE   49856                   // 16 f
#define W2F_BYTE   49920                   // W2^T fp16: 128 x 272B
#define SMEM_BYTES 84736

__global__ void __launch_bounds__(TPB, 1)
sde_hmma(const float* __restrict__ z0, const float* __restrict__ activity,
         const float* __restrict__ rest, const float* __restrict__ ts,
         const float* __restrict__ noise,
         const float* __restrict__ aW1, const float* __restrict__ ab1,
         const float* __restrict__ aW2, const float* __restrict__ ab2,
         const float* __restrict__ rW1, const float* __restrict__ rb1,
         const float* __restrict__ rW2, const float* __restrict__ rb2,
         const float* __restrict__ dW1, const float* __restrict__ db1,
         const float* __restrict__ dW2, const float* __restrict__ db2,
         const float* __restrict__ dW3, const float* __restrict__ db3,
         const float* __restrict__ gW1, const float* __restrict__ gb1,
         const float* __restrict__ gW2, const float* __restrict__ gb2,
         float* __restrict__ out, int Bn, int nstep)
{
    extern __shared__ char smc[];
    const uint32_t sbase = smem_u32(smc);
    const int tid  = threadIdx.x;
    const int wid  = tid >> 5;
    const int lane = tid & 31;
    const int gid  = lane >> 2;            // 0..7 fragment row group
    const int tid4 = lane & 3;
    const int qc   = tid4 * 2;             // fragment col pair base
    const int half = lane >> 4;            // 0/1 half-warp
    const int eidx = lane & 15;            // element within warp
    const int elemBase = blockIdx.x * EPC + wid * 16;
    const int elemS    = elemBase + eidx;  // my element (scalar phases)
    const bool active  = (elemBase < Bn);  // warp-uniform
    const int gw = blockIdx.x * NWARP + wid;

    // ================= one-time staging =================
    // W2^T fp16: BT[n][k] at n*272 + 2k
    for (int i = tid; i < 16384; i += TPB) {
        int k = i >> 7, n = i & 127;
        *(__half*)(smc + W2F_BYTE + (uint32_t)n * 272u + (uint32_t)k * 2u) =
            __float2half_rn(dW2[i]);
    }
    if (tid < 128) {
        // W1T row n=tid: k0..9 = hi(dW1[j][n]), k10..19 = lo, k20..29 = hi, rest 0
        __nv_bfloat16* r = (__nv_bfloat16*)(smc + W1T_BYTE + tid * 80);
        #pragma unroll
        for (int k = 0; k < 40; ++k) r[k] = __float2bfloat16(0.0f);
        #pragma unroll
        for (int j = 0; j < 10; ++j) {
            float w = dW1[j * 128 + tid];
            __nv_bfloat16 hi = __float2bfloat16(w);
            __nv_bfloat16 lo = __float2bfloat16(w - __bfloat162float(hi));
            r[j] = hi; r[10 + j] = lo; r[20 + j] = hi;
        }
        ((float*)(smc + WT_BYTE))[tid]  = dW1[106 * 128 + tid];
        ((float*)(smc + DB2_BYTE))[tid] = db2[tid];
        float* w3r = (float*)(smc + W3P_BYTE + tid * 48);
        #pragma unroll
        for (int j = 0; j < 10; ++j) w3r[j] = dW3[tid * 10 + j];
        w3r[10] = 0.0f; w3r[11] = 0.0f;
    }
    if (tid < 32) {
        float* g1r = (float*)(smc + GW1_BYTE + tid * 48);
        #pragma unroll
        for (int j = 0; j < 10; ++j) g1r[j] = gW1[j * 32 + tid];
        g1r[10] = gW1[10 * 32 + tid];
        g1r[11] = 0.0f;
        float* g2r = (float*)(smc + GW2_BYTE + tid * 48);
        #pragma unroll
        for (int j = 0; j < 10; ++j) g2r[j] = gW2[tid * 10 + j];
        g2r[10] = 0.0f; g2r[11] = 0.0f;
        ((float*)(smc + GB1_BYTE))[tid] = gb1[tid];
    }
    if (tid < 16) {
        ((float*)(smc + GB2_BYTE))[tid] = (tid < 10) ? gb2[tid] : 0.0f;
        ((float*)(smc + DB3_BYTE))[tid] = (tid < 10) ? db3[tid] : 0.0f;
    }
    for (int i = tid; i <= nstep && i < 128; i += TPB)
        ((float*)(smc + TS_BYTE))[i] = ts[i];

    // ---- context encoders -> C[128] -> g_C [col4][elem] (first 224 threads) ----
    if (tid < EPC) {
        const int elemE = blockIdx.x * EPC + tid;
        if (elemE < Bn) {
            float actv[6], rsv[3];
            #pragma unroll
            for (int j = 0; j < 6; ++j) actv[j] = activity[elemE * 6 + j];
            #pragma unroll
            for (int j = 0; j < 3; ++j) rsv[j] = rest[elemE * 3 + j];
            float ha[32];
            #pragma unroll
            for (int o = 0; o < 32; ++o) {
                float q = __ldg(&ab1[o]);
                #pragma unroll
                for (int j = 0; j < 6; ++j) q += actv[j] * __ldg(&aW1[j * 32 + o]);
                ha[o] = fmaxf(q, 0.0f);
            }
            float av[64];
            #pragma unroll
            for (int o = 0; o < 64; ++o) {
                float q = __ldg(&ab2[o]);
                #pragma unroll
                for (int j = 0; j < 32; ++j) q += ha[j] * __ldg(&aW2[j * 64 + o]);
                av[o] = q;
            }
            float hr[16];
            #pragma unroll
            for (int o = 0; o < 16; ++o) {
                float q = __ldg(&rb1[o]);
                #pragma unroll
                for (int j = 0; j < 3; ++j) q += rsv[j] * __ldg(&rW1[j * 16 + o]);
                hr[o] = fmaxf(q, 0.0f);
            }
            float rv[32];
            #pragma unroll
            for (int o = 0; o < 32; ++o) {
                float q = __ldg(&rb2[o]);
                #pragma unroll
                for (int j = 0; j < 16; ++j) q += hr[j] * __ldg(&rW2[j * 32 + o]);
                rv[o] = q;
            }
            for (int o4 = 0; o4 < 32; ++o4) {
                float cv[4];
                #pragma unroll
                for (int c = 0; c < 4; ++c) {
                    int o = o4 * 4 + c;
                    float q = __ldg(&db1[o]);
                    #pragma unroll
                    for (int j = 0; j < 64; ++j) q += av[j] * __ldg(&dW1[(10 + j) * 128 + o]);
                    #pragma unroll
                    for (int j = 0; j < 32; ++j) q += rv[j] * __ldg(&dW1[(74 + j) * 128 + o]);
                    cv[c] = q;
                }
                g_C[(size_t)o4 * Bn + elemE] = make_float4(cv[0], cv[1], cv[2], cv[3]);
            }
        }
    }
    __syncthreads();   // g_C visible CTA-wide; smem staged

    float z[10];
    if (active) {
        // ---- repack C into fragment layout g_Cf (M=16 tile) ----
        #pragma unroll
        for (int nt = 0; nt < 16; ++nt) {
            int R0 = elemBase + gid;
            int o4 = 2 * nt + (tid4 >> 1);
            float4 v0 = g_C[(size_t)o4 * Bn + R0];
            float4 v1 = g_C[(size_t)o4 * Bn + R0 + 8];
            float4 fr;
            if (tid4 & 1) { fr.x = v0.z; fr.y = v0.w; fr.z = v1.z; fr.w = v1.w; }
            else          { fr.x = v0.x; fr.y = v0.y; fr.z = v1.x; fr.w = v1.y; }
            g_Cf[((size_t)gw * 16 + nt) * 32 + lane] = fr;
        }
        // z0 (both halves) + output row 0 (half 0 only)
        #pragma unroll
        for (int j = 0; j < 10; ++j) z[j] = z0[elemS * 10 + j];
        if (half == 0) {
            float2* op0 = (float2*)(out + (size_t)elemS * 10);
            #pragma unroll
            for (int j = 0; j < 5; ++j) op0[j] = make_float2(z[2 * j], z[2 * j + 1]);
        }
    }
    if (!active) return;    // no further __syncthreads

    // precomputed addresses
    const uint32_t zwarp = sbase + ZBUF_BYTE + (uint32_t)wid * (16 * 80);
    const uint32_t zaL   = zwarp + (uint32_t)eidx * 80u + (uint32_t)half * 16u;
    const uint32_t w1L   = sbase + W1T_BYTE + (uint32_t)(lane & 7) * 80u
                         + (((uint32_t)lane >> 3) & 1u) * 16u + (uint32_t)half * 640u;
    const uint32_t bLdmLane = (uint32_t)(lane & 7) * 272u + ((uint32_t)lane >> 3) * 16u;
    float* route = (float*)(smc + ROUTE_BYTE + wid * 16 * 48);
    const float* tsf = (const float*)(smc + TS_BYTE);
    const float4* cfp = &g_Cf[(size_t)gw * 16 * 32 + lane];

    // ================= SDE integration (warp-synchronous) =================
    for (int s = 0; s < nstep; ++s) {
        const float t  = tsf[s];
        const float dt = tsf[s + 1] - t;
        const float sq = sqrtf(dt);

        // ---- z-aug row: [z_hi | z_hi | z_lo | 0] as 16 bf16x2; halves split chunks ----
        {
            unsigned short hs[10]; float zl[10];
            #pragma unroll
            for (int j = 0; j < 10; ++j) {
                __nv_bfloat16 h = __float2bfloat16(z[j]);
                hs[j] = __bfloat16_as_ushort(h);
                zl[j] = z[j] - __bfloat162float(h);
            }
            uint32_t p[16];
            #pragma unroll
            for (int i = 0; i < 5; ++i) {
                p[i] = (uint32_t)hs[2 * i] | ((uint32_t)hs[2 * i + 1] << 16);
                p[5 + i] = p[i];
                p[10 + i] = bf16x2_of(zl[2 * i], zl[2 * i + 1]);
            }
            p[15] = 0u;
            uint32_t dst = zwarp + (uint32_t)eidx * 80u + (uint32_t)half * 32u;
            const int b = half * 8;
            asm volatile("st.shared.v4.b32 [%0], {%1,%2,%3,%4};" :: "r"(dst),
                "r"(p[b + 0]), "r"(p[b + 1]), "r"(p[b + 2]), "r"(p[b + 3]));
            asm volatile("st.shared.v4.b32 [%0], {%1,%2,%3,%4};" :: "r"(dst + 16),
                "r"(p[b + 4]), "r"(p[b + 5]), "r"(p[b + 6]), "r"(p[b + 7]));
        }
        __syncwarp();

        uint32_t za[2][4];
        #pragma unroll
        for (int ks = 0; ks < 2; ++ks)
            ldm_x4(za[ks], zaL + (uint32_t)ks * 32u);

        // ---- GEMM1: h1 = tanh(zaug @ W1T + C + t*wt) -> fp16 A-frags in regs ----
        uint32_t af[8][4];
        {
            float a1[16][4];
            #pragma unroll
            for (int nt = 0; nt < 16; ++nt) {
                float4 cf = __ldg(cfp + nt * 32);
                float2 w2 = *(const float2*)(smc + WT_BYTE + (nt * 8 + qc) * 4);
                a1[nt][0] = fmaf(t, w2.x, cf.x);
                a1[nt][1] = fmaf(t, w2.y, cf.y);
                a1[nt][2] = fmaf(t, w2.x, cf.z);
                a1[nt][3] = fmaf(t, w2.y, cf.w);
            }
            #pragma unroll
            for (int ks = 0; ks < 2; ++ks)
                #pragma unroll
                for (int i = 0; i < 8; ++i) {
                    uint32_t bw[4];
                    ldm_x4(bw, w1L + (uint32_t)i * 1280u + (uint32_t)ks * 32u);
                    mma_bf16(a1[2 * i],     za[ks], bw[0], bw[1]);
                    mma_bf16(a1[2 * i + 1], za[ks], bw[2], bw[3]);
                }
            #pragma unroll
            for (int kt = 0; kt < 8; ++kt) {
                af[kt][0] = f16x2_of(tanh_hw(a1[2 * kt][0]),     tanh_hw(a1[2 * kt][1]));
                af[kt][1] = f16x2_of(tanh_hw(a1[2 * kt][2]),     tanh_hw(a1[2 * kt][3]));
                af[kt][2] = f16x2_of(tanh_hw(a1[2 * kt + 1][0]), tanh_hw(a1[2 * kt + 1][1]));
                af[kt][3] = f16x2_of(tanh_hw(a1[2 * kt + 1][2]), tanh_hw(a1[2 * kt + 1][3]));
            }
        }

        // ---- GEMM2 (fp16 single pass) + scalar epilogue ----
        ull dzp[2][5];
        #pragma unroll
        for (int ss = 0; ss < 2; ++ss)
            #pragma unroll
            for (int jj = 0; jj < 5; ++jj) dzp[ss][jj] = pack2(0.0f, 0.0f);

        #pragma unroll
        for (int ng = 0; ng < 4; ++ng) {
            float acc[4][4];
            #pragma unroll
            for (int ni = 0; ni < 4; ++ni) {
                float2 d2 = *(const float2*)(smc + DB2_BYTE + ((ng * 4 + ni) * 8 + qc) * 4);
                acc[ni][0] = d2.x; acc[ni][1] = d2.y;
                acc[ni][2] = d2.x; acc[ni][3] = d2.y;
            }
            #pragma unroll
            for (int ni = 0; ni < 4; ++ni) {
                const uint32_t brow = sbase + W2F_BYTE + bLdmLane
                                    + (uint32_t)((ng * 4 + ni) * 8) * 272u;
                #pragma unroll
                for (int ktp = 0; ktp < 4; ++ktp) {
                    uint32_t r[4];
                    ldm_x4(r, brow + (uint32_t)ktp * 64u);
                    mma_f16(acc[ni], af[2 * ktp],     r[0], r[1]);
                    mma_f16(acc[ni], af[2 * ktp + 1], r[2], r[3]);
                }
            }
            #pragma unroll
            for (int ni = 0; ni < 4; ++ni) {
                const int cb = (ng * 4 + ni) * 8 + qc;
                const ull* w3a = (const ull*)(smc + W3P_BYTE + cb * 48);
                const ull* w3b = (const ull*)(smc + W3P_BYTE + (cb + 1) * 48);
                float h0 = tanh_hw(acc[ni][0]);
                float h1 = tanh_hw(acc[ni][1]);
                float h2 = tanh_hw(acc[ni][2]);
                float h3 = tanh_hw(acc[ni][3]);
                ull p0 = pack2(h0, h0), p1 = pack2(h1, h1);
                ull p2 = pack2(h2, h2), p3 = pack2(h3, h3);
                #pragma unroll
                for (int jj = 0; jj < 5; ++jj) {
                    dzp[0][jj] = ffma2(p0, w3a[jj], dzp[0][jj]);
                    dzp[0][jj] = ffma2(p1, w3b[jj], dzp[0][jj]);
                    dzp[1][jj] = ffma2(p2, w3a[jj], dzp[1][jj]);
                    dzp[1][jj] = ffma2(p3, w3b[jj], dzp[1][jj]);
                }
            }
        }

        // ---- quad reduce + route dz to owner lane ----
        float dzf[2][10];
        #pragma unroll
        for (int ss = 0; ss < 2; ++ss)
            #pragma unroll
            for (int jj = 0; jj < 5; ++jj)
                unpack2(dzp[ss][jj], dzf[ss][2 * jj], dzf[ss][2 * jj + 1]);
        #pragma unroll
        for (int ss = 0; ss < 2; ++ss)
            #pragma unroll
            for (int j = 0; j < 10; ++j) {
                float v = dzf[ss][j];
                v += __shfl_xor_sync(0xffffffffu, v, 1);
                v += __shfl_xor_sync(0xffffffffu, v, 2);
                dzf[ss][j] = v;
            }
        if (tid4 == 0) {
            #pragma unroll
            for (int ss = 0; ss < 2; ++ss) {
                const int row = ss * 8 + gid;
                float2* rp = (float2*)(route + row * 12);
                #pragma unroll
                for (int jj = 0; jj < 5; ++jj)
                    rp[jj] = make_float2(dzf[ss][2 * jj], dzf[ss][2 * jj + 1]);
            }
        }
        __syncwarp();
        float dz[10];
        {
            const float* rp = route + eidx * 12;
            const float* d3 = (const float*)(smc + DB3_BYTE);
            #pragma unroll
            for (int j = 0; j < 10; ++j) dz[j] = rp[j] + d3[j];
        }
        __syncwarp();

        // ---- diffusion MLP 11 -> 32 -> 10 (o-range split across halves) ----
        ull zp[5];
        #pragma unroll
        for (int j = 0; j < 5; ++j) zp[j] = pack2(z[2 * j], z[2 * j + 1]);
        ull gvp[5];
        {
            const float2* g2 = (const float2*)(smc + GB2_BYTE);
            #pragma unroll
            for (int jj = 0; jj < 5; ++jj)
                gvp[jj] = half ? pack2(0.0f, 0.0f) : pack2(g2[jj].x, g2[jj].y);
        }
        const float* gb1f = (const float*)(smc + GB1_BYTE);
        const int o0 = half * 16;
        #pragma unroll 4
        for (int oi = 0; oi < 16; ++oi) {
            const int o = o0 + oi;
            const float4* g1 = (const float4*)(smc + GW1_BYTE + o * 48);
            float4 w0 = g1[0], w4 = g1[1], w8 = g1[2];
            ull p2 = pack2(gb1f[o], t * w8.z);
            p2 = ffma2(zp[0], pack2(w0.x, w0.y), p2);
            p2 = ffma2(zp[1], pack2(w0.z, w0.w), p2);
            p2 = ffma2(zp[2], pack2(w4.x, w4.y), p2);
            p2 = ffma2(zp[3], pack2(w4.z, w4.w), p2);
            p2 = ffma2(zp[4], pack2(w8.x, w8.y), p2);
            float plo, phi; unpack2(p2, plo, phi);
            float q = softplus_(plo + phi);
            ull qq = pack2(q, q);
            const ull* g2w = (const ull*)(smc + GW2_BYTE + o * 48);
            #pragma unroll
            for (int jj = 0; jj < 5; ++jj) gvp[jj] = ffma2(qq, g2w[jj], gvp[jj]);
        }
        // combine halves
        float gv[10];
        #pragma unroll
        for (int jj = 0; jj < 5; ++jj) unpack2(gvp[jj], gv[2 * jj], gv[2 * jj + 1]);
        #pragma unroll
        for (int j = 0; j < 10; ++j)
            gv[j] += __shfl_xor_sync(0xffffffffu, gv[j], 16);

        // ---- Euler-Maruyama update (both halves) + stream out (half 0) ----
        const float2* np = (const float2*)(noise + ((size_t)s * Bn + elemS) * 10);
        float2*       op = (float2*)(out + ((size_t)(s + 1) * Bn + elemS) * 10);
        #pragma unroll
        for (int j = 0; j < 5; ++j) {
            float2 e = np[j];
            z[2 * j]     += dz[2 * j]     * dt + gv[2 * j]     * sq * e.x;
            z[2 * j + 1] += dz[2 * j + 1] * dt + gv[2 * j + 1] * sq * e.y;
            if (half == 0) op[j] = make_float2(z[2 * j], z[2 * j + 1]);
        }
    }
}

extern "C" void kernel_launch(void* const* d_in, const int* in_sizes, int n_in,
                              void* d_out, int out_size) {
    const float* z0       = (const float*)d_in[0];
    const float* activity = (const float*)d_in[1];
    const float* rest     = (const float*)d_in[2];
    const float* ts       = (const float*)d_in[3];
    const float* noise    = (const float*)d_in[4];
    const float* aW1 = (const float*)d_in[5];
    const float* ab1 = (const float*)d_in[6];
    const float* aW2 = (const float*)d_in[7];
    const float* ab2 = (const float*)d_in[8];
    const float* rW1 = (const float*)d_in[9];
    const float* rb1 = (const float*)d_in[10];
    const float* rW2 = (const float*)d_in[11];
    const float* rb2 = (const float*)d_in[12];
    const float* dW1 = (const float*)d_in[13];
    const float* db1 = (const float*)d_in[14];
    const float* dW2 = (const float*)d_in[15];
    const float* db2 = (const float*)d_in[16];
    const float* dW3 = (const float*)d_in[17];
    const float* db3 = (const float*)d_in[18];
    const float* gW1 = (const float*)d_in[19];
    const float* gb1 = (const float*)d_in[20];
    const float* gW2 = (const float*)d_in[21];
    const float* gb2 = (const float*)d_in[22];

    int B     = in_sizes[0] / 10;
    int nstep = in_sizes[3] - 1;

    cudaFuncSetAttribute(sde_hmma, cudaFuncAttributeMaxDynamicSharedMemorySize,
                         SMEM_BYTES);
    int grid = (B + EPC - 1) / EPC;
    sde_hmma<<<grid, TPB, SMEM_BYTES>>>(
        z0, activity, rest, ts, noise,
        aW1, ab1, aW2, ab2, rW1, rb1, rW2, rb2,
        dW1, db1, dW2, db2, dW3, db3,
        gW1, gb1, gW2, gb2,
        (float*)d_out, B, nstep);
}

// round 12
// speedup vs baseline: 1.3118x; 1.3067x over previous
#include <cuda_runtime.h>
#include <cuda_bf16.h>
#include <cuda_fp16.h>
#include <cstdint>
#include <cstddef>

#define TPB 448
#define NWARP 14
#define EPC 224          // elements per CTA (14 warps x 16)

typedef unsigned long long ull;

// C context: [col/4][elem] float4 (intermediate), and fragment-packed per warp.
__device__ float4 g_C[32 * 32768];
__device__ float4 g_Cf[2058 * 16 * 32];   // [gwarp][nt][lane]

// ---------------- packed f32x2 ----------------
__device__ __forceinline__ ull ffma2(ull a, ull b, ull c) {
    ull d; asm("fma.rn.f32x2 %0, %1, %2, %3;" : "=l"(d) : "l"(a), "l"(b), "l"(c)); return d;
}
__device__ __forceinline__ ull pack2(float lo, float hi) {
    ull r; asm("mov.b64 %0, {%1, %2};" : "=l"(r) : "f"(lo), "f"(hi)); return r;
}
__device__ __forceinline__ void unpack2(ull v, float& lo, float& hi) {
    asm("mov.b64 {%0, %1}, %2;" : "=f"(lo), "=f"(hi) : "l"(v));
}
__device__ __forceinline__ uint32_t bf16x2_of(float lo, float hi) {
    uint32_t r; asm("cvt.rn.bf16x2.f32 %0, %1, %2;" : "=r"(r) : "f"(hi), "f"(lo)); return r;
}
__device__ __forceinline__ uint32_t f16x2_of(float lo, float hi) {
    uint32_t r; asm("cvt.rn.f16x2.f32 %0, %1, %2;" : "=r"(r) : "f"(hi), "f"(lo)); return r;
}
__device__ __forceinline__ float tanh_hw(float x) {
    float y; asm("tanh.approx.f32 %0, %1;" : "=f"(y) : "f"(x)); return y;
}
__device__ __forceinline__ float softplus_(float x) {
    return fmaxf(x, 0.0f) + __logf(1.0f + __expf(-fabsf(x)));
}
// bf16 mma (GEMM1, exact hi/lo split path)
__device__ __forceinline__ void mma_bf16(float* c, const uint32_t* a, uint32_t b0, uint32_t b1) {
    asm volatile("mma.sync.aligned.m16n8k16.row.col.f32.bf16.bf16.f32 "
        "{%0,%1,%2,%3}, {%4,%5,%6,%7}, {%8,%9}, {%0,%1,%2,%3};"
        : "+f"(c[0]), "+f"(c[1]), "+f"(c[2]), "+f"(c[3])
        : "r"(a[0]), "r"(a[1]), "r"(a[2]), "r"(a[3]), "r"(b0), "r"(b1));
}
// fp16 mma (GEMM2 single pass, GEMM3)
__device__ __forceinline__ void mma_f16(float* c, const uint32_t* a, uint32_t b0, uint32_t b1) {
    asm volatile("mma.sync.aligned.m16n8k16.row.col.f32.f16.f16.f32 "
        "{%0,%1,%2,%3}, {%4,%5,%6,%7}, {%8,%9}, {%0,%1,%2,%3};"
        : "+f"(c[0]), "+f"(c[1]), "+f"(c[2]), "+f"(c[3])
        : "r"(a[0]), "r"(a[1]), "r"(a[2]), "r"(a[3]), "r"(b0), "r"(b1));
}
__device__ __forceinline__ void ldm_x4(uint32_t* r, uint32_t addr) {
    asm volatile("ldmatrix.sync.aligned.m8n8.x4.shared.b16 {%0,%1,%2,%3}, [%4];"
        : "=r"(r[0]), "=r"(r[1]), "=r"(r[2]), "=r"(r[3]) : "r"(addr));
}
__device__ __forceinline__ uint32_t smem_u32(const void* p) {
    uint32_t a;
    asm("{ .reg .u64 t; cvta.to.shared.u64 t, %1; cvt.u32.u64 %0, t; }" : "=r"(a) : "l"(p));
    return a;
}

// ---------------- SMEM byte layout ----------------
#define ZBUF_BYTE  0                       // 14 warps x 16 rows x 80B
#define W1T_BYTE   17920                   // 128 n-rows x 80B (bf16: hi|lo|hi|0)
#define ROUTE_BYTE 28160                   // 14 warps x 16 rows x 72B (stride-18 floats)
#define DB2_BYTE   44288                   // 128 f
#define WT_BYTE    44800                   // 128 f (t-row of dW1, fp32)
#define GW1_BYTE   45312                   // [32][12] f
#define GW2_BYTE   46848                   // [32][12] f
#define GB1_BYTE   48384                   // 32 f
#define TS_BYTE    48512                   // 128 f
#define GB2_BYTE   49024                   // 16 f
#define DB3_BYTE   49088                   // 16 f
#define W2F_BYTE   49152                   // W2^T fp16: 128 x 272B
#define SMEM_BYTES 83968

__global__ void __launch_bounds__(TPB, 1)
sde_hmma(const float* __restrict__ z0, const float* __restrict__ activity,
         const float* __restrict__ rest, const float* __restrict__ ts,
         const float* __restrict__ noise,
         const float* __restrict__ aW1, const float* __restrict__ ab1,
         const float* __restrict__ aW2, const float* __restrict__ ab2,
         const float* __restrict__ rW1, const float* __restrict__ rb1,
         const float* __restrict__ rW2, const float* __restrict__ rb2,
         const float* __restrict__ dW1, const float* __restrict__ db1,
         const float* __restrict__ dW2, const float* __restrict__ db2,
         const float* __restrict__ dW3, const float* __restrict__ db3,
         const float* __restrict__ gW1, const float* __restrict__ gb1,
         const float* __restrict__ gW2, const float* __restrict__ gb2,
         float* __restrict__ out, int Bn, int nstep)
{
    extern __shared__ char smc[];
    const uint32_t sbase = smem_u32(smc);
    const int tid  = threadIdx.x;
    const int wid  = tid >> 5;
    const int lane = tid & 31;
    const int gid  = lane >> 2;            // 0..7 fragment row group
    const int tid4 = lane & 3;
    const int qc   = tid4 * 2;             // fragment col pair base
    const int half = lane >> 4;            // 0/1 half-warp
    const int eidx = lane & 15;            // element within warp
    const int elemBase = blockIdx.x * EPC + wid * 16;
    const int elemS    = elemBase + eidx;  // my element (scalar phases)
    const bool active  = (elemBase < Bn);  // warp-uniform
    const int gw = blockIdx.x * NWARP + wid;

    // ================= one-time staging =================
    // W2^T fp16: BT[n][k] at n*272 + 2k
    for (int i = tid; i < 16384; i += TPB) {
        int k = i >> 7, n = i & 127;
        *(__half*)(smc + W2F_BYTE + (uint32_t)n * 272u + (uint32_t)k * 2u) =
            __float2half_rn(dW2[i]);
    }
    if (tid < 128) {
        // W1T row n=tid: k0..9 = hi(dW1[j][n]), k10..19 = lo, k20..29 = hi, rest 0
        __nv_bfloat16* r = (__nv_bfloat16*)(smc + W1T_BYTE + tid * 80);
        #pragma unroll
        for (int k = 0; k < 40; ++k) r[k] = __float2bfloat16(0.0f);
        #pragma unroll
        for (int j = 0; j < 10; ++j) {
            float w = dW1[j * 128 + tid];
            __nv_bfloat16 hi = __float2bfloat16(w);
            __nv_bfloat16 lo = __float2bfloat16(w - __bfloat162float(hi));
            r[j] = hi; r[10 + j] = lo; r[20 + j] = hi;
        }
        ((float*)(smc + WT_BYTE))[tid]  = dW1[106 * 128 + tid];
        ((float*)(smc + DB2_BYTE))[tid] = db2[tid];
    }
    if (tid < 32) {
        float* g1r = (float*)(smc + GW1_BYTE + tid * 48);
        #pragma unroll
        for (int j = 0; j < 10; ++j) g1r[j] = gW1[j * 32 + tid];
        g1r[10] = gW1[10 * 32 + tid];
        g1r[11] = 0.0f;
        float* g2r = (float*)(smc + GW2_BYTE + tid * 48);
        #pragma unroll
        for (int j = 0; j < 10; ++j) g2r[j] = gW2[tid * 10 + j];
        g2r[10] = 0.0f; g2r[11] = 0.0f;
        ((float*)(smc + GB1_BYTE))[tid] = gb1[tid];
    }
    if (tid < 16) {
        ((float*)(smc + GB2_BYTE))[tid] = (tid < 10) ? gb2[tid] : 0.0f;
        ((float*)(smc + DB3_BYTE))[tid] = (tid < 10) ? db3[tid] : 0.0f;
    }
    for (int i = tid; i <= nstep && i < 128; i += TPB)
        ((float*)(smc + TS_BYTE))[i] = ts[i];

    // ---- context encoders -> C[128] -> g_C [col4][elem] (first 224 threads) ----
    if (tid < EPC) {
        const int elemE = blockIdx.x * EPC + tid;
        if (elemE < Bn) {
            float actv[6], rsv[3];
            #pragma unroll
            for (int j = 0; j < 6; ++j) actv[j] = activity[elemE * 6 + j];
            #pragma unroll
            for (int j = 0; j < 3; ++j) rsv[j] = rest[elemE * 3 + j];
            float ha[32];
            #pragma unroll
            for (int o = 0; o < 32; ++o) {
                float q = __ldg(&ab1[o]);
                #pragma unroll
                for (int j = 0; j < 6; ++j) q += actv[j] * __ldg(&aW1[j * 32 + o]);
                ha[o] = fmaxf(q, 0.0f);
            }
            float av[64];
            #pragma unroll
            for (int o = 0; o < 64; ++o) {
                float q = __ldg(&ab2[o]);
                #pragma unroll
                for (int j = 0; j < 32; ++j) q += ha[j] * __ldg(&aW2[j * 64 + o]);
                av[o] = q;
            }
            float hr[16];
            #pragma unroll
            for (int o = 0; o < 16; ++o) {
                float q = __ldg(&rb1[o]);
                #pragma unroll
                for (int j = 0; j < 3; ++j) q += rsv[j] * __ldg(&rW1[j * 16 + o]);
                hr[o] = fmaxf(q, 0.0f);
            }
            float rv[32];
            #pragma unroll
            for (int o = 0; o < 32; ++o) {
                float q = __ldg(&rb2[o]);
                #pragma unroll
                for (int j = 0; j < 16; ++j) q += hr[j] * __ldg(&rW2[j * 32 + o]);
                rv[o] = q;
            }
            for (int o4 = 0; o4 < 32; ++o4) {
                float cv[4];
                #pragma unroll
                for (int c = 0; c < 4; ++c) {
                    int o = o4 * 4 + c;
                    float q = __ldg(&db1[o]);
                    #pragma unroll
                    for (int j = 0; j < 64; ++j) q += av[j] * __ldg(&dW1[(10 + j) * 128 + o]);
                    #pragma unroll
                    for (int j = 0; j < 32; ++j) q += rv[j] * __ldg(&dW1[(74 + j) * 128 + o]);
                    cv[c] = q;
                }
                g_C[(size_t)o4 * Bn + elemE] = make_float4(cv[0], cv[1], cv[2], cv[3]);
            }
        }
    }
    __syncthreads();   // g_C visible CTA-wide; smem staged

    float z[10];
    if (active) {
        // ---- repack C into fragment layout g_Cf (M=16 tile) ----
        #pragma unroll
        for (int nt = 0; nt < 16; ++nt) {
            int R0 = elemBase + gid;
            int o4 = 2 * nt + (tid4 >> 1);
            float4 v0 = g_C[(size_t)o4 * Bn + R0];
            float4 v1 = g_C[(size_t)o4 * Bn + R0 + 8];
            float4 fr;
            if (tid4 & 1) { fr.x = v0.z; fr.y = v0.w; fr.z = v1.z; fr.w = v1.w; }
            else          { fr.x = v0.x; fr.y = v0.y; fr.z = v1.x; fr.w = v1.y; }
            g_Cf[((size_t)gw * 16 + nt) * 32 + lane] = fr;
        }
        // z0 (both halves) + output row 0 (half 0 only)
        #pragma unroll
        for (int j = 0; j < 10; ++j) z[j] = z0[elemS * 10 + j];
        if (half == 0) {
            float2* op0 = (float2*)(out + (size_t)elemS * 10);
            #pragma unroll
            for (int j = 0; j < 5; ++j) op0[j] = make_float2(z[2 * j], z[2 * j + 1]);
        }
    }
    if (!active) return;    // no further __syncthreads

    // ---- W3 B-fragments for GEMM3, held in registers across all steps ----
    // GEMM3: dz[16 elem x 16] = tanh(h2)[16 x 128] @ W3[128 x 16(10 padded)]
    uint32_t b3[8][2][2];
    #pragma unroll
    for (int kt = 0; kt < 8; ++kt)
        #pragma unroll
        for (int nt = 0; nt < 2; ++nt) {
            const int n = nt * 8 + gid;
            float w00 = 0.f, w01 = 0.f, w10 = 0.f, w11 = 0.f;
            if (n < 10) {
                w00 = dW3[(16 * kt + 2 * tid4)     * 10 + n];
                w01 = dW3[(16 * kt + 2 * tid4 + 1) * 10 + n];
                w10 = dW3[(16 * kt + 8 + 2 * tid4)     * 10 + n];
                w11 = dW3[(16 * kt + 8 + 2 * tid4 + 1) * 10 + n];
            }
            b3[kt][nt][0] = f16x2_of(w00, w01);
            b3[kt][nt][1] = f16x2_of(w10, w11);
        }
    // db3 in fragment-col registers (smem DB3 has zeros in 10..15)
    float d3r[4];
    {
        const float* d3 = (const float*)(smc + DB3_BYTE);
        d3r[0] = d3[qc]; d3r[1] = d3[qc + 1];
        d3r[2] = d3[8 + qc]; d3r[3] = d3[8 + qc + 1];
    }

    // precomputed addresses
    const uint32_t zwarp = sbase + ZBUF_BYTE + (uint32_t)wid * (16 * 80);
    const uint32_t zaL   = zwarp + (uint32_t)eidx * 80u + (uint32_t)half * 16u;
    const uint32_t w1L   = sbase + W1T_BYTE + (uint32_t)(lane & 7) * 80u
                         + (((uint32_t)lane >> 3) & 1u) * 16u + (uint32_t)half * 640u;
    const uint32_t bLdmLane = (uint32_t)(lane & 7) * 272u + ((uint32_t)lane >> 3) * 16u;
    const uint32_t routeW = sbase + ROUTE_BYTE + (uint32_t)wid * (16 * 72);
    const float* tsf = (const float*)(smc + TS_BYTE);
    const float4* cfp = &g_Cf[(size_t)gw * 16 * 32 + lane];

    // ================= SDE integration (warp-synchronous) =================
    for (int s = 0; s < nstep; ++s) {
        const float t  = tsf[s];
        const float dt = tsf[s + 1] - t;
        const float sq = sqrtf(dt);

        // ---- z-aug row: [z_hi | z_hi | z_lo | 0] as 16 bf16x2; halves split chunks ----
        {
            unsigned short hs[10]; float zl[10];
            #pragma unroll
            for (int j = 0; j < 10; ++j) {
                __nv_bfloat16 h = __float2bfloat16(z[j]);
                hs[j] = __bfloat16_as_ushort(h);
                zl[j] = z[j] - __bfloat162float(h);
            }
            uint32_t p[16];
            #pragma unroll
            for (int i = 0; i < 5; ++i) {
                p[i] = (uint32_t)hs[2 * i] | ((uint32_t)hs[2 * i + 1] << 16);
                p[5 + i] = p[i];
                p[10 + i] = bf16x2_of(zl[2 * i], zl[2 * i + 1]);
            }
            p[15] = 0u;
            uint32_t dst = zwarp + (uint32_t)eidx * 80u + (uint32_t)half * 32u;
            const int b = half * 8;
            asm volatile("st.shared.v4.b32 [%0], {%1,%2,%3,%4};" :: "r"(dst),
                "r"(p[b + 0]), "r"(p[b + 1]), "r"(p[b + 2]), "r"(p[b + 3]));
            asm volatile("st.shared.v4.b32 [%0], {%1,%2,%3,%4};" :: "r"(dst + 16),
                "r"(p[b + 4]), "r"(p[b + 5]), "r"(p[b + 6]), "r"(p[b + 7]));
        }
        __syncwarp();

        uint32_t za[2][4];
        #pragma unroll
        for (int ks = 0; ks < 2; ++ks)
            ldm_x4(za[ks], zaL + (uint32_t)ks * 32u);

        // ---- GEMM1: h1 = tanh(zaug @ W1T + C + t*wt) -> fp16 A-frags in regs ----
        uint32_t af[8][4];
        {
            float a1[16][4];
            #pragma unroll
            for (int nt = 0; nt < 16; ++nt) {
                float4 cf = __ldg(cfp + nt * 32);
                float2 w2 = *(const float2*)(smc + WT_BYTE + (nt * 8 + qc) * 4);
                a1[nt][0] = fmaf(t, w2.x, cf.x);
                a1[nt][1] = fmaf(t, w2.y, cf.y);
                a1[nt][2] = fmaf(t, w2.x, cf.z);
                a1[nt][3] = fmaf(t, w2.y, cf.w);
            }
            #pragma unroll
            for (int ks = 0; ks < 2; ++ks)
                #pragma unroll
                for (int i = 0; i < 8; ++i) {
                    uint32_t bw[4];
                    ldm_x4(bw, w1L + (uint32_t)i * 1280u + (uint32_t)ks * 32u);
                    mma_bf16(a1[2 * i],     za[ks], bw[0], bw[1]);
                    mma_bf16(a1[2 * i + 1], za[ks], bw[2], bw[3]);
                }
            #pragma unroll
            for (int kt = 0; kt < 8; ++kt) {
                af[kt][0] = f16x2_of(tanh_hw(a1[2 * kt][0]),     tanh_hw(a1[2 * kt][1]));
                af[kt][1] = f16x2_of(tanh_hw(a1[2 * kt][2]),     tanh_hw(a1[2 * kt][3]));
                af[kt][2] = f16x2_of(tanh_hw(a1[2 * kt + 1][0]), tanh_hw(a1[2 * kt + 1][1]));
                af[kt][3] = f16x2_of(tanh_hw(a1[2 * kt + 1][2]), tanh_hw(a1[2 * kt + 1][3]));
            }
        }

        // ---- GEMM2 (fp16) fused with GEMM3 (dz = tanh(h2) @ W3) ----
        float acc3[2][4];
        acc3[0][0] = d3r[0]; acc3[0][1] = d3r[1]; acc3[0][2] = d3r[0]; acc3[0][3] = d3r[1];
        acc3[1][0] = d3r[2]; acc3[1][1] = d3r[3]; acc3[1][2] = d3r[2]; acc3[1][3] = d3r[3];

        #pragma unroll
        for (int ng = 0; ng < 4; ++ng) {
            float acc[4][4];
            #pragma unroll
            for (int ni = 0; ni < 4; ++ni) {
                float2 d2 = *(const float2*)(smc + DB2_BYTE + ((ng * 4 + ni) * 8 + qc) * 4);
                acc[ni][0] = d2.x; acc[ni][1] = d2.y;
                acc[ni][2] = d2.x; acc[ni][3] = d2.y;
            }
            #pragma unroll
            for (int ni = 0; ni < 4; ++ni) {
                const uint32_t brow = sbase + W2F_BYTE + bLdmLane
                                    + (uint32_t)((ng * 4 + ni) * 8) * 272u;
                #pragma unroll
                for (int ktp = 0; ktp < 4; ++ktp) {
                    uint32_t r[4];
                    ldm_x4(r, brow + (uint32_t)ktp * 64u);
                    mma_f16(acc[ni], af[2 * ktp],     r[0], r[1]);
                    mma_f16(acc[ni], af[2 * ktp + 1], r[2], r[3]);
                }
            }
            // GEMM3: acc fragments ARE A-fragments (after tanh + f16 pack)
            #pragma unroll
            for (int p = 0; p < 2; ++p) {
                uint32_t a3[4];
                a3[0] = f16x2_of(tanh_hw(acc[2 * p][0]),     tanh_hw(acc[2 * p][1]));
                a3[1] = f16x2_of(tanh_hw(acc[2 * p][2]),     tanh_hw(acc[2 * p][3]));
                a3[2] = f16x2_of(tanh_hw(acc[2 * p + 1][0]), tanh_hw(acc[2 * p + 1][1]));
                a3[3] = f16x2_of(tanh_hw(acc[2 * p + 1][2]), tanh_hw(acc[2 * p + 1][3]));
                const int kt = 2 * ng + p;
                mma_f16(acc3[0], a3, b3[kt][0][0], b3[kt][0][1]);
                mma_f16(acc3[1], a3, b3[kt][1][0], b3[kt][1][1]);
            }
        }

        // ---- route dz fragments to owner lanes (stride-18f rows, conflict-free) ----
        {
            uint32_t r0 = routeW + (uint32_t)gid * 72u;
            uint32_t r1 = routeW + (uint32_t)(gid + 8) * 72u;
            asm volatile("st.shared.v2.f32 [%0], {%1,%2};" :: "r"(r0 + qc * 4),
                "f"(acc3[0][0]), "f"(acc3[0][1]));
            asm volatile("st.shared.v2.f32 [%0], {%1,%2};" :: "r"(r0 + (8 + qc) * 4),
                "f"(acc3[1][0]), "f"(acc3[1][1]));
            asm volatile("st.shared.v2.f32 [%0], {%1,%2};" :: "r"(r1 + qc * 4),
                "f"(acc3[0][2]), "f"(acc3[0][3]));
            asm volatile("st.shared.v2.f32 [%0], {%1,%2};" :: "r"(r1 + (8 + qc) * 4),
                "f"(acc3[1][2]), "f"(acc3[1][3]));
        }
        __syncwarp();
        float dz[10];
        {
            const uint32_t rp = routeW + (uint32_t)eidx * 72u;
            #pragma unroll
            for (int jj = 0; jj < 5; ++jj) {
                float2 v;
                asm volatile("ld.shared.v2.f32 {%0,%1}, [%2];"
                    : "=f"(v.x), "=f"(v.y) : "r"(rp + jj * 8));
                dz[2 * jj] = v.x; dz[2 * jj + 1] = v.y;
            }
        }
        __syncwarp();

        // ---- diffusion MLP 11 -> 32 -> 10 (o-range split across halves) ----
        ull zp[5];
        #pragma unroll
        for (int j = 0; j < 5; ++j) zp[j] = pack2(z[2 * j], z[2 * j + 1]);
        ull gvp[5];
        {
            const float2* g2 = (const float2*)(smc + GB2_BYTE);
            #pragma unroll
            for (int jj = 0; jj < 5; ++jj)
                gvp[jj] = half ? pack2(0.0f, 0.0f) : pack2(g2[jj].x, g2[jj].y);
        }
        const float* gb1f = (const float*)(smc + GB1_BYTE);
        const int o0 = half * 16;
        #pragma unroll 4
        for (int oi = 0; oi < 16; ++oi) {
            const int o = o0 + oi;
            const float4* g1 = (const float4*)(smc + GW1_BYTE + o * 48);
            float4 w0 = g1[0], w4 = g1[1], w8 = g1[2];
            ull p2 = pack2(gb1f[o], t * w8.z);
            p2 = ffma2(zp[0], pack2(w0.x, w0.y), p2);
            p2 = ffma2(zp[1], pack2(w0.z, w0.w), p2);
            p2 = ffma2(zp[2], pack2(w4.x, w4.y), p2);
            p2 = ffma2(zp[3], pack2(w4.z, w4.w), p2);
            p2 = ffma2(zp[4], pack2(w8.x, w8.y), p2);
            float plo, phi; unpack2(p2, plo, phi);
            float q = softplus_(plo + phi);
            ull qq = pack2(q, q);
            const ull* g2w = (const ull*)(smc + GW2_BYTE + o * 48);
            #pragma unroll
            for (int jj = 0; jj < 5; ++jj) gvp[jj] = ffma2(qq, g2w[jj], gvp[jj]);
        }
        // combine halves
        float gv[10];
        #pragma unroll
        for (int jj = 0; jj < 5; ++jj) unpack2(gvp[jj], gv[2 * jj], gv[2 * jj + 1]);
        #pragma unroll
        for (int j = 0; j < 10; ++j)
            gv[j] += __shfl_xor_sync(0xffffffffu, gv[j], 16);

        // ---- Euler-Maruyama update (both halves) + stream out (half 0) ----
        const float2* np = (const float2*)(noise + ((size_t)s * Bn + elemS) * 10);
        float2*       op = (float2*)(out + ((size_t)(s + 1) * Bn + elemS) * 10);
        #pragma unroll
        for (int j = 0; j < 5; ++j) {
            float2 e = np[j];
            z[2 * j]     += dz[2 * j]     * dt + gv[2 * j]     * sq * e.x;
            z[2 * j + 1] += dz[2 * j + 1] * dt + gv[2 * j + 1] * sq * e.y;
            if (half == 0) op[j] = make_float2(z[2 * j], z[2 * j + 1]);
        }
    }
}

extern "C" void kernel_launch(void* const* d_in, const int* in_sizes, int n_in,
                              void* d_out, int out_size) {
    const float* z0       = (const float*)d_in[0];
    const float* activity = (const float*)d_in[1];
    const float* rest     = (const float*)d_in[2];
    const float* ts       = (const float*)d_in[3];
    const float* noise    = (const float*)d_in[4];
    const float* aW1 = (const float*)d_in[5];
    const float* ab1 = (const float*)d_in[6];
    const float* aW2 = (const float*)d_in[7];
    const float* ab2 = (const float*)d_in[8];
    const float* rW1 = (const float*)d_in[9];
    const float* rb1 = (const float*)d_in[10];
    const float* rW2 = (const float*)d_in[11];
    const float* rb2 = (const float*)d_in[12];
    const float* dW1 = (const float*)d_in[13];
    const float* db1 = (const float*)d_in[14];
    const float* dW2 = (const float*)d_in[15];
    const float* db2 = (const float*)d_in[16];
    const float* dW3 = (const float*)d_in[17];
    const float* db3 = (const float*)d_in[18];
    const float* gW1 = (const float*)d_in[19];
    const float* gb1 = (const float*)d_in[20];
    const float* gW2 = (const float*)d_in[21];
    const float* gb2 = (const float*)d_in[22];

    int B     = in_sizes[0] / 10;
    int nstep = in_sizes[3] - 1;

    cudaFuncSetAttribute(sde_hmma, cudaFuncAttributeMaxDynamicSharedMemorySize,
                         SMEM_BYTES);
    int grid = (B + EPC - 1) / EPC;
    sde_hmma<<<grid, TPB, SMEM_BYTES>>>(
        z0, activity, rest, ts, noise,
        aW1, ab1, aW2, ab2, rW1, rb1, rW2, rb2,
        dW1, db1, dW2, db2, dW3, db3,
        gW1, gb1, gW2, gb2,
        (float*)d_out, B, nstep);
}

// round 14
// speedup vs baseline: 1.3196x; 1.0060x over previous
#include <cuda_runtime.h>
#include <cuda_bf16.h>
#include <cuda_fp16.h>
#include <cstdint>
#include <cstddef>

#define TPB 448
#define NWARP 14
#define EPC 224          // elements per CTA (14 warps x 16)

typedef unsigned long long ull;

// ---------------- helpers ----------------
__device__ __forceinline__ uint32_t f16x2_of(float lo, float hi) {
    uint32_t r; asm("cvt.rn.f16x2.f32 %0, %1, %2;" : "=r"(r) : "f"(hi), "f"(lo)); return r;
}
__device__ __forceinline__ uint32_t tanh2(uint32_t x) {
    uint32_t y; asm("tanh.approx.f16x2 %0, %1;" : "=r"(y) : "r"(x)); return y;
}
__device__ __forceinline__ float softplus_(float x) {
    return fmaxf(x, 0.0f) + __logf(1.0f + __expf(-fabsf(x)));
}
__device__ __forceinline__ void mma_f16(float* c, const uint32_t* a, uint32_t b0, uint32_t b1) {
    asm volatile("mma.sync.aligned.m16n8k16.row.col.f32.f16.f16.f32 "
        "{%0,%1,%2,%3}, {%4,%5,%6,%7}, {%8,%9}, {%0,%1,%2,%3};"
        : "+f"(c[0]), "+f"(c[1]), "+f"(c[2]), "+f"(c[3])
        : "r"(a[0]), "r"(a[1]), "r"(a[2]), "r"(a[3]), "r"(b0), "r"(b1));
}
__device__ __forceinline__ void ldm_x4(uint32_t* r, uint32_t addr) {
    asm volatile("ldmatrix.sync.aligned.m8n8.x4.shared.b16 {%0,%1,%2,%3}, [%4];"
        : "=r"(r[0]), "=r"(r[1]), "=r"(r[2]), "=r"(r[3]) : "r"(addr));
}
__device__ __forceinline__ uint32_t smem_u32(const void* p) {
    uint32_t a;
    asm("{ .reg .u64 t; cvta.to.shared.u64 t, %1; cvt.u32.u64 %0, t; }" : "=r"(a) : "l"(p));
    return a;
}

// ---------------- SMEM byte layout ----------------
#define ZBUF_BYTE   0                        // 14 warps x 16 rows x 48B (fp16 z, 16 cols)
#define W1EXT_BYTE  10752                    // 160 n-rows x 48B fp16 (k16: W1|gW1 cols)
#define W3T_BYTE    18432                    // 16 n-rows x 272B fp16 (k128)  [dW3^T]
#define CF_BYTE     22784                    // 14 warps x 16nt x 32 lanes x 16B (C frags)
#define ROUTE_BYTE  137472                   // 14 x 16 x 128B (dz n0..15 @0, gv n0..15 @64)
#define W2F_BYTE    166144                   // W2^T fp16: 128 x 272B
#define DB2_BYTE    200960                   // 128 f
#define WT_BYTE     201472                   // 128 f (t-row of dW1)
#define GWT_BYTE    201984                   // 32 f (t-row of gW1)
#define GB1_BYTE    202112                   // 32 f
#define GB2_BYTE    202240                   // 16 f (pad 0)
#define DB3_BYTE    202304                   // 16 f (pad 0)
#define TS_BYTE     202368                   // 128 f
#define SMEM_BYTES  202880

__global__ void __launch_bounds__(TPB, 1)
sde_hmma(const float* __restrict__ z0, const float* __restrict__ activity,
         const float* __restrict__ rest, const float* __restrict__ ts,
         const float* __restrict__ noise,
         const float* __restrict__ aW1, const float* __restrict__ ab1,
         const float* __restrict__ aW2, const float* __restrict__ ab2,
         const float* __restrict__ rW1, const float* __restrict__ rb1,
         const float* __restrict__ rW2, const float* __restrict__ rb2,
         const float* __restrict__ dW1, const float* __restrict__ db1,
         const float* __restrict__ dW2, const float* __restrict__ db2,
         const float* __restrict__ dW3, const float* __restrict__ db3,
         const float* __restrict__ gW1, const float* __restrict__ gb1,
         const float* __restrict__ gW2, const float* __restrict__ gb2,
         float* __restrict__ out, int Bn, int nstep)
{
    extern __shared__ char smc[];
    const uint32_t sbase = smem_u32(smc);
    const int tid  = threadIdx.x;
    const int wid  = tid >> 5;
    const int lane = tid & 31;
    const int gid  = lane >> 2;
    const int tid4 = lane & 3;
    const int qc   = tid4 * 2;
    const int half = lane >> 4;
    const int eidx = lane & 15;
    const int elemBase = blockIdx.x * EPC + wid * 16;
    const int elemS    = elemBase + eidx;
    const bool active  = (elemBase < Bn);

    // ================= one-time staging =================
    for (int i = tid; i < 16384; i += TPB) {
        int k = i >> 7, n = i & 127;
        *(__half*)(smc + W2F_BYTE + (uint32_t)n * 272u + (uint32_t)k * 2u) =
            __float2half_rn(dW2[i]);
    }
    if (tid < 160) {   // W1EXT rows: 0..127 drift, 128..159 diffusion
        __half* r = (__half*)(smc + W1EXT_BYTE + tid * 48);
        #pragma unroll
        for (int k = 0; k < 24; ++k) r[k] = __float2half_rn(0.0f);
        if (tid < 128) {
            #pragma unroll
            for (int j = 0; j < 10; ++j) r[j] = __float2half_rn(dW1[j * 128 + tid]);
        } else {
            #pragma unroll
            for (int j = 0; j < 10; ++j) r[j] = __float2half_rn(gW1[j * 32 + (tid - 128)]);
        }
    }
    if (tid < 16) {    // W3T: [n][k] fp16, n rows 16 (10 real), k 128
        __half* r = (__half*)(smc + W3T_BYTE + tid * 272);
        for (int k = 0; k < 136; ++k) r[k] = __float2half_rn(0.0f);
        if (tid < 10)
            for (int k = 0; k < 128; ++k) r[k] = __float2half_rn(dW3[k * 10 + tid]);
    }
    if (tid < 128) {
        ((float*)(smc + WT_BYTE))[tid]  = dW1[106 * 128 + tid];
        ((float*)(smc + DB2_BYTE))[tid] = db2[tid];
    }
    if (tid < 32) {
        ((float*)(smc + GWT_BYTE))[tid] = gW1[10 * 32 + tid];
        ((float*)(smc + GB1_BYTE))[tid] = gb1[tid];
    }
    if (tid < 16) {
        ((float*)(smc + GB2_BYTE))[tid] = (tid < 10) ? gb2[tid] : 0.0f;
        ((float*)(smc + DB3_BYTE))[tid] = (tid < 10) ? db3[tid] : 0.0f;
    }
    for (int i = tid; i <= nstep && i < 128; i += TPB)
        ((float*)(smc + TS_BYTE))[i] = ts[i];

    // ---- context encoders -> C[128] scattered into CF fragment layout ----
    if (tid < EPC) {
        const int elemE = blockIdx.x * EPC + tid;
        if (elemE < Bn) {
            float actv[6], rsv[3];
            #pragma unroll
            for (int j = 0; j < 6; ++j) actv[j] = activity[elemE * 6 + j];
            #pragma unroll
            for (int j = 0; j < 3; ++j) rsv[j] = rest[elemE * 3 + j];
            float ha[32];
            #pragma unroll
            for (int o = 0; o < 32; ++o) {
                float q = __ldg(&ab1[o]);
                #pragma unroll
                for (int j = 0; j < 6; ++j) q += actv[j] * __ldg(&aW1[j * 32 + o]);
                ha[o] = fmaxf(q, 0.0f);
            }
            float av[64];
            #pragma unroll
            for (int o = 0; o < 64; ++o) {
                float q = __ldg(&ab2[o]);
                #pragma unroll
                for (int j = 0; j < 32; ++j) q += ha[j] * __ldg(&aW2[j * 64 + o]);
                av[o] = q;
            }
            float hr[16];
            #pragma unroll
            for (int o = 0; o < 16; ++o) {
                float q = __ldg(&rb1[o]);
                #pragma unroll
                for (int j = 0; j < 3; ++j) q += rsv[j] * __ldg(&rW1[j * 16 + o]);
                hr[o] = fmaxf(q, 0.0f);
            }
            float rv[32];
            #pragma unroll
            for (int o = 0; o < 32; ++o) {
                float q = __ldg(&rb2[o]);
                #pragma unroll
                for (int j = 0; j < 16; ++j) q += hr[j] * __ldg(&rW2[j * 32 + o]);
                rv[o] = q;
            }
            const int w = tid >> 4, r = tid & 15;
            const uint32_t cfw = sbase + CF_BYTE + (uint32_t)w * 8192u;
            const int laneb = (r & 7) << 2;
            const int inner = (r >= 8) ? 8 : 0;
            for (int o4 = 0; o4 < 32; ++o4) {
                float cv[4];
                #pragma unroll
                for (int c = 0; c < 4; ++c) {
                    int o = o4 * 4 + c;
                    float q = __ldg(&db1[o]);
                    #pragma unroll
                    for (int j = 0; j < 64; ++j) q += av[j] * __ldg(&dW1[(10 + j) * 128 + o]);
                    #pragma unroll
                    for (int j = 0; j < 32; ++j) q += rv[j] * __ldg(&dW1[(74 + j) * 128 + o]);
                    cv[c] = q;
                }
                const int nt = o4 >> 1;
                const int t4b = 2 * (o4 & 1);
                uint32_t a0 = cfw + (uint32_t)((nt * 32 + laneb + t4b) * 16 + inner);
                uint32_t a1a = cfw + (uint32_t)((nt * 32 + laneb + t4b + 1) * 16 + inner);
                asm volatile("st.shared.v2.f32 [%0], {%1,%2};" :: "r"(a0), "f"(cv[0]), "f"(cv[1]));
                asm volatile("st.shared.v2.f32 [%0], {%1,%2};" :: "r"(a1a), "f"(cv[2]), "f"(cv[3]));
            }
        }
    }
    __syncthreads();

    float z[10];
    if (active) {
        #pragma unroll
        for (int j = 0; j < 10; ++j) z[j] = z0[elemS * 10 + j];
        if (half == 0) {
            float2* op0 = (float2*)(out + (size_t)elemS * 10);
            #pragma unroll
            for (int j = 0; j < 5; ++j) op0[j] = make_float2(z[2 * j], z[2 * j + 1]);
        }
    }
    if (!active) return;

    // ---- gW2 B-fragments (registers, fixed) ----
    uint32_t gB[2][2][2];
    #pragma unroll
    for (int kt = 0; kt < 2; ++kt)
        #pragma unroll
        for (int nt = 0; nt < 2; ++nt) {
            const int n = nt * 8 + gid;
            float w00 = 0.f, w01 = 0.f, w10 = 0.f, w11 = 0.f;
            if (n < 10) {
                w00 = gW2[(16 * kt + 2 * tid4)     * 10 + n];
                w01 = gW2[(16 * kt + 2 * tid4 + 1) * 10 + n];
                w10 = gW2[(16 * kt + 2 * tid4 + 8) * 10 + n];
                w11 = gW2[(16 * kt + 2 * tid4 + 9) * 10 + n];
            }
            gB[kt][nt][0] = f16x2_of(w00, w01);
            gB[kt][nt][1] = f16x2_of(w10, w11);
        }
    float d3r[4], ga[4];
    {
        const float* d3 = (const float*)(smc + DB3_BYTE);
        const float* g2 = (const float*)(smc + GB2_BYTE);
        d3r[0] = d3[qc]; d3r[1] = d3[qc + 1]; d3r[2] = d3[8 + qc]; d3r[3] = d3[9 + qc];
        ga[0]  = g2[qc]; ga[1]  = g2[qc + 1]; ga[2]  = g2[8 + qc]; ga[3]  = g2[9 + qc];
    }

    // precomputed addresses
    const uint32_t zwarp = sbase + ZBUF_BYTE + (uint32_t)wid * (16 * 48);
    const uint32_t zaL   = zwarp + (uint32_t)eidx * 48u + (uint32_t)half * 16u;
    const uint32_t zstore = zwarp + (uint32_t)eidx * 48u + (uint32_t)half * 16u;
    const uint32_t w1L   = sbase + W1EXT_BYTE + (uint32_t)(lane & 7) * 48u
                         + (((uint32_t)lane >> 3) & 1u) * 16u + (uint32_t)half * 384u;
    const uint32_t w3tL  = sbase + W3T_BYTE + (uint32_t)(lane & 7) * 272u
                         + ((uint32_t)lane >> 3) * 16u;
    const uint32_t bLdmLane = (uint32_t)(lane & 7) * 272u + ((uint32_t)lane >> 3) * 16u;
    const uint32_t cfW   = sbase + CF_BYTE + (uint32_t)wid * 8192u + (uint32_t)lane * 16u;
    const uint32_t routeW = sbase + ROUTE_BYTE + (uint32_t)wid * (16 * 128);
    const float* tsf = (const float*)(smc + TS_BYTE);

    // ================= SDE integration (warp-synchronous) =================
    for (int s = 0; s < nstep; ++s) {
        const float t  = tsf[s];
        const float dt = tsf[s + 1] - t;
        const float sq = sqrtf(dt);

        // ---- z row fp16 (16 cols: z0..9, 0...) ----
        {
            uint32_t p0 = f16x2_of(z[0], z[1]);
            uint32_t p1 = f16x2_of(z[2], z[3]);
            uint32_t p2 = f16x2_of(z[4], z[5]);
            uint32_t p3 = f16x2_of(z[6], z[7]);
            uint32_t p4 = f16x2_of(z[8], z[9]);
            uint32_t q0 = half ? p4 : p0;
            uint32_t q1 = half ? 0u : p1;
            uint32_t q2 = half ? 0u : p2;
            uint32_t q3 = half ? 0u : p3;
            asm volatile("st.shared.v4.b32 [%0], {%1,%2,%3,%4};"
                :: "r"(zstore), "r"(q0), "r"(q1), "r"(q2), "r"(q3));
        }
        __syncwarp();
        uint32_t za[4];
        ldm_x4(za, zaL);

        // ---- GEMM1 drift: h1 = tanh(z@W1 + C + t*wt), two n-halves ----
        uint32_t af[8][4];
        #pragma unroll
        for (int hd = 0; hd < 2; ++hd) {
            float a1[8][4];
            #pragma unroll
            for (int nt = 0; nt < 8; ++nt) {
                const int gnt = 8 * hd + nt;
                float4 cf;
                asm volatile("ld.shared.v4.f32 {%0,%1,%2,%3}, [%4];"
                    : "=f"(cf.x), "=f"(cf.y), "=f"(cf.z), "=f"(cf.w)
                    : "r"(cfW + (uint32_t)gnt * 512u));
                float2 w2 = *(const float2*)(smc + WT_BYTE + (gnt * 8 + qc) * 4);
                a1[nt][0] = fmaf(t, w2.x, cf.x);
                a1[nt][1] = fmaf(t, w2.y, cf.y);
                a1[nt][2] = fmaf(t, w2.x, cf.z);
                a1[nt][3] = fmaf(t, w2.y, cf.w);
            }
            #pragma unroll
            for (int i = 0; i < 4; ++i) {
                uint32_t bw[4];
                ldm_x4(bw, w1L + (uint32_t)(8 * hd + 2 * i) * 384u);
                mma_f16(a1[2 * i],     za, bw[0], bw[1]);
                mma_f16(a1[2 * i + 1], za, bw[2], bw[3]);
            }
            #pragma unroll
            for (int kt = 0; kt < 4; ++kt) {
                af[4 * hd + kt][0] = tanh2(f16x2_of(a1[2 * kt][0],     a1[2 * kt][1]));
                af[4 * hd + kt][1] = tanh2(f16x2_of(a1[2 * kt][2],     a1[2 * kt][3]));
                af[4 * hd + kt][2] = tanh2(f16x2_of(a1[2 * kt + 1][0], a1[2 * kt + 1][1]));
                af[4 * hd + kt][3] = tanh2(f16x2_of(a1[2 * kt + 1][2], a1[2 * kt + 1][3]));
            }
        }

        // ---- diffusion layer 1 via GEMM1 extension + softplus + GEMM-g ----
        float accg[2][4];
        {
            float ag[4][4];
            const float* gb1f = (const float*)(smc + GB1_BYTE);
            const float* gwtf = (const float*)(smc + GWT_BYTE);
            #pragma unroll
            for (int nt = 0; nt < 4; ++nt) {
                const int c0 = nt * 8 + qc;
                float b0 = fmaf(t, gwtf[c0],     gb1f[c0]);
                float b1 = fmaf(t, gwtf[c0 + 1], gb1f[c0 + 1]);
                ag[nt][0] = b0; ag[nt][1] = b1; ag[nt][2] = b0; ag[nt][3] = b1;
            }
            #pragma unroll
            for (int i = 0; i < 2; ++i) {
                uint32_t bw[4];
                ldm_x4(bw, w1L + (uint32_t)(128 + 16 * i) * 48u);
                mma_f16(ag[2 * i],     za, bw[0], bw[1]);
                mma_f16(ag[2 * i + 1], za, bw[2], bw[3]);
            }
            uint32_t qf[2][4];
            #pragma unroll
            for (int kt = 0; kt < 2; ++kt) {
                qf[kt][0] = f16x2_of(softplus_(ag[2 * kt][0]),     softplus_(ag[2 * kt][1]));
                qf[kt][1] = f16x2_of(softplus_(ag[2 * kt][2]),     softplus_(ag[2 * kt][3]));
                qf[kt][2] = f16x2_of(softplus_(ag[2 * kt + 1][0]), softplus_(ag[2 * kt + 1][1]));
                qf[kt][3] = f16x2_of(softplus_(ag[2 * kt + 1][2]), softplus_(ag[2 * kt + 1][3]));
            }
            accg[0][0] = ga[0]; accg[0][1] = ga[1]; accg[0][2] = ga[0]; accg[0][3] = ga[1];
            accg[1][0] = ga[2]; accg[1][1] = ga[3]; accg[1][2] = ga[2]; accg[1][3] = ga[3];
            #pragma unroll
            for (int kt = 0; kt < 2; ++kt) {
                mma_f16(accg[0], qf[kt], gB[kt][0][0], gB[kt][0][1]);
                mma_f16(accg[1], qf[kt], gB[kt][1][0], gB[kt][1][1]);
            }
        }

        // ---- GEMM2 (h2) fused with GEMM3 (dz) ----
        float acc3[2][4];
        acc3[0][0] = d3r[0]; acc3[0][1] = d3r[1]; acc3[0][2] = d3r[0]; acc3[0][3] = d3r[1];
        acc3[1][0] = d3r[2]; acc3[1][1] = d3r[3]; acc3[1][2] = d3r[2]; acc3[1][3] = d3r[3];
        #pragma unroll
        for (int ng = 0; ng < 4; ++ng) {
            float acc[4][4];
            #pragma unroll
            for (int ni = 0; ni < 4; ++ni) {
                float2 d2 = *(const float2*)(smc + DB2_BYTE + ((ng * 4 + ni) * 8 + qc) * 4);
                acc[ni][0] = d2.x; acc[ni][1] = d2.y;
                acc[ni][2] = d2.x; acc[ni][3] = d2.y;
            }
            #pragma unroll
            for (int ni = 0; ni < 4; ++ni) {
                const uint32_t brow = sbase + W2F_BYTE + bLdmLane
                                    + (uint32_t)((ng * 4 + ni) * 8) * 272u;
                #pragma unroll
                for (int ktp = 0; ktp < 4; ++ktp) {
                    uint32_t r[4];
                    ldm_x4(r, brow + (uint32_t)ktp * 64u);
                    mma_f16(acc[ni], af[2 * ktp],     r[0], r[1]);
                    mma_f16(acc[ni], af[2 * ktp + 1], r[2], r[3]);
                }
            }
            uint32_t r3a[4], r3b[4];
            ldm_x4(r3a, w3tL + (uint32_t)ng * 64u);
            ldm_x4(r3b, w3tL + 8 * 272u + (uint32_t)ng * 64u);
            #pragma unroll
            for (int p = 0; p < 2; ++p) {
                uint32_t a3[4];
                a3[0] = tanh2(f16x2_of(acc[2 * p][0],     acc[2 * p][1]));
                a3[1] = tanh2(f16x2_of(acc[2 * p][2],     acc[2 * p][3]));
                a3[2] = tanh2(f16x2_of(acc[2 * p + 1][0], acc[2 * p + 1][1]));
                a3[3] = tanh2(f16x2_of(acc[2 * p + 1][2], acc[2 * p + 1][3]));
                mma_f16(acc3[0], a3, r3a[2 * p], r3a[2 * p + 1]);
                mma_f16(acc3[1], a3, r3b[2 * p], r3b[2 * p + 1]);
            }
        }

        // ---- route dz + gv fragments to owner lanes (128B rows; dz [0,64), gv [64,128)) ----
        {
            uint32_t r0 = routeW + (uint32_t)gid * 128u;
            uint32_t r1 = routeW + (uint32_t)(gid + 8) * 128u;
            asm volatile("st.shared.v2.f32 [%0], {%1,%2};" :: "r"(r0 + qc * 4),
                "f"(acc3[0][0]), "f"(acc3[0][1]));
            asm volatile("st.shared.v2.f32 [%0], {%1,%2};" :: "r"(r0 + 32 + qc * 4),
                "f"(acc3[1][0]), "f"(acc3[1][1]));
            asm volatile("st.shared.v2.f32 [%0], {%1,%2};" :: "r"(r1 + qc * 4),
                "f"(acc3[0][2]), "f"(acc3[0][3]));
            asm volatile("st.shared.v2.f32 [%0], {%1,%2};" :: "r"(r1 + 32 + qc * 4),
                "f"(acc3[1][2]), "f"(acc3[1][3]));
            asm volatile("st.shared.v2.f32 [%0], {%1,%2};" :: "r"(r0 + 64 + qc * 4),
                "f"(accg[0][0]), "f"(accg[0][1]));
            asm volatile("st.shared.v2.f32 [%0], {%1,%2};" :: "r"(r0 + 96 + qc * 4),
                "f"(accg[1][0]), "f"(accg[1][1]));
            asm volatile("st.shared.v2.f32 [%0], {%1,%2};" :: "r"(r1 + 64 + qc * 4),
                "f"(accg[0][2]), "f"(accg[0][3]));
            asm volatile("st.shared.v2.f32 [%0], {%1,%2};" :: "r"(r1 + 96 + qc * 4),
                "f"(accg[1][2]), "f"(accg[1][3]));
        }
        __syncwarp();
        float dz[10], gv[10];
        {
            const uint32_t rp = routeW + (uint32_t)eidx * 128u;
            #pragma unroll
            for (int jj = 0; jj < 5; ++jj) {
                float2 v;
                asm volatile("ld.shared.v2.f32 {%0,%1}, [%2];"
                    : "=f"(v.x), "=f"(v.y) : "r"(rp + jj * 8));
                dz[2 * jj] = v.x; dz[2 * jj + 1] = v.y;
                float2 g;
                asm volatile("ld.shared.v2.f32 {%0,%1}, [%2];"
                    : "=f"(g.x), "=f"(g.y) : "r"(rp + 64 + jj * 8));
                gv[2 * jj] = g.x; gv[2 * jj + 1] = g.y;
            }
        }
        __syncwarp();

        // ---- Euler-Maruyama update (both halves) + stream out (half 0) ----
        const float2* np = (const float2*)(noise + ((size_t)s * Bn + elemS) * 10);
        float2*       op = (float2*)(out + ((size_t)(s + 1) * Bn + elemS) * 10);
        #pragma unroll
        for (int j = 0; j < 5; ++j) {
            float2 e = np[j];
            z[2 * j]     += dz[2 * j]     * dt + gv[2 * j]     * sq * e.x;
            z[2 * j + 1] += dz[2 * j + 1] * dt + gv[2 * j + 1] * sq * e.y;
            if (half == 0) op[j] = make_float2(z[2 * j], z[2 * j + 1]);
        }
    }
}

extern "C" void kernel_launch(void* const* d_in, const int* in_sizes, int n_in,
                              void* d_out, int out_size) {
    const float* z0       = (const float*)d_in[0];
    const float* activity = (const float*)d_in[1];
    const float* rest     = (const float*)d_in[2];
    const float* ts       = (const float*)d_in[3];
    const float* noise    = (const float*)d_in[4];
    const float* aW1 = (const float*)d_in[5];
    const float* ab1 = (const float*)d_in[6];
    const float* aW2 = (const float*)d_in[7];
    const float* ab2 = (const float*)d_in[8];
    const float* rW1 = (const float*)d_in[9];
    const float* rb1 = (const float*)d_in[10];
    const float* rW2 = (const float*)d_in[11];
    const float* rb2 = (const float*)d_in[12];
    const float* dW1 = (const float*)d_in[13];
    const float* db1 = (const float*)d_in[14];
    const float* dW2 = (const float*)d_in[15];
    const float* db2 = (const float*)d_in[16];
    const float* dW3 = (const float*)d_in[17];
    const float* db3 = (const float*)d_in[18];
    const float* gW1 = (const float*)d_in[19];
    const float* gb1 = (const float*)d_in[20];
    const float* gW2 = (const float*)d_in[21];
    const float* gb2 = (const float*)d_in[22];

    int B     = in_sizes[0] / 10;
    int nstep = in_sizes[3] - 1;

    cudaFuncSetAttribute(sde_hmma, cudaFuncAttributeMaxDynamicSharedMemorySize,
                         SMEM_BYTES);
    int grid = (B + EPC - 1) / EPC;
    sde_hmma<<<grid, TPB, SMEM_BYTES>>>(
        z0, activity, rest, ts, noise,
        aW1, ab1, aW2, ab2, rW1, rb1, rW2, rb2,
        dW1, db1, dW2, db2, dW3, db3,
        gW1, gb1, gW2, gb2,
        (float*)d_out, B, nstep);
}

// round 15
// speedup vs baseline: 1.8112x; 1.3725x over previous
#include <cuda_runtime.h>
#include <cuda_bf16.h>
#include <cuda_fp16.h>
#include <cstdint>
#include <cstddef>

#define TPB 448
#define NWARP 14
#define EPC 224          // elements per CTA (14 warps x 16)

// ---------------- helpers ----------------
__device__ __forceinline__ uint32_t f16x2_of(float lo, float hi) {
    uint32_t r; asm("cvt.rn.f16x2.f32 %0, %1, %2;" : "=r"(r) : "f"(hi), "f"(lo)); return r;
}
__device__ __forceinline__ uint32_t tanh2(uint32_t x) {
    uint32_t y; asm("tanh.approx.f16x2 %0, %1;" : "=r"(y) : "r"(x)); return y;
}
__device__ __forceinline__ float softplus_(float x) {
    return fmaxf(x, 0.0f) + __logf(1.0f + __expf(-fabsf(x)));
}
__device__ __forceinline__ void mma_f16(float* c, const uint32_t* a, uint32_t b0, uint32_t b1) {
    asm volatile("mma.sync.aligned.m16n8k16.row.col.f32.f16.f16.f32 "
        "{%0,%1,%2,%3}, {%4,%5,%6,%7}, {%8,%9}, {%0,%1,%2,%3};"
        : "+f"(c[0]), "+f"(c[1]), "+f"(c[2]), "+f"(c[3])
        : "r"(a[0]), "r"(a[1]), "r"(a[2]), "r"(a[3]), "r"(b0), "r"(b1));
}
__device__ __forceinline__ void ldm_x4(uint32_t* r, uint32_t addr) {
    asm volatile("ldmatrix.sync.aligned.m8n8.x4.shared.b16 {%0,%1,%2,%3}, [%4];"
        : "=r"(r[0]), "=r"(r[1]), "=r"(r[2]), "=r"(r[3]) : "r"(addr));
}
__device__ __forceinline__ uint32_t smem_u32(const void* p) {
    uint32_t a;
    asm("{ .reg .u64 t; cvta.to.shared.u64 t, %1; cvt.u32.u64 %0, t; }" : "=r"(a) : "l"(p));
    return a;
}

// ---------------- SMEM byte layout ----------------
#define W1EXT_BYTE  0                        // 160 n-rows x 48B fp16 (k16: W1|gW1 cols)
#define W3T_BYTE    7680                     // 16 n-rows x 272B fp16 (k128)  [dW3^T]
#define CF_BYTE     12032                    // 14 warps x 16nt x 32 lanes x 16B (C frags)
#define W2F_BYTE    126720                   // W2^T fp16: 128 x 272B
#define DB2_BYTE    161536                   // 128 f
#define WT_BYTE     162048                   // 128 f (t-row of dW1)
#define GWT_BYTE    162560                   // 32 f (t-row of gW1)
#define GB1_BYTE    162688                   // 32 f
#define GB2_BYTE    162816                   // 16 f (pad 0)
#define DB3_BYTE    162880                   // 16 f (pad 0)
#define TS_BYTE     162944                   // 128 f
#define SMEM_BYTES  163456

__global__ void __launch_bounds__(TPB, 1)
sde_hmma(const float* __restrict__ z0, const float* __restrict__ activity,
         const float* __restrict__ rest, const float* __restrict__ ts,
         const float* __restrict__ noise,
         const float* __restrict__ aW1, const float* __restrict__ ab1,
         const float* __restrict__ aW2, const float* __restrict__ ab2,
         const float* __restrict__ rW1, const float* __restrict__ rb1,
         const float* __restrict__ rW2, const float* __restrict__ rb2,
         const float* __restrict__ dW1, const float* __restrict__ db1,
         const float* __restrict__ dW2, const float* __restrict__ db2,
         const float* __restrict__ dW3, const float* __restrict__ db3,
         const float* __restrict__ gW1, const float* __restrict__ gb1,
         const float* __restrict__ gW2, const float* __restrict__ gb2,
         float* __restrict__ out, int Bn, int nstep)
{
    extern __shared__ char smc[];
    const uint32_t sbase = smem_u32(smc);
    const int tid  = threadIdx.x;
    const int wid  = tid >> 5;
    const int lane = tid & 31;
    const int gid  = lane >> 2;
    const int tid4 = lane & 3;
    const int qc   = tid4 * 2;
    const int elemBase = blockIdx.x * EPC + wid * 16;
    const bool active  = (elemBase < Bn);

    // ================= one-time staging =================
    for (int i = tid; i < 16384; i += TPB) {
        int k = i >> 7, n = i & 127;
        *(__half*)(smc + W2F_BYTE + (uint32_t)n * 272u + (uint32_t)k * 2u) =
            __float2half_rn(dW2[i]);
    }
    if (tid < 160) {   // W1EXT rows: 0..127 drift, 128..159 diffusion
        __half* r = (__half*)(smc + W1EXT_BYTE + tid * 48);
        #pragma unroll
        for (int k = 0; k < 24; ++k) r[k] = __float2half_rn(0.0f);
        if (tid < 128) {
            #pragma unroll
            for (int j = 0; j < 10; ++j) r[j] = __float2half_rn(dW1[j * 128 + tid]);
        } else {
            #pragma unroll
            for (int j = 0; j < 10; ++j) r[j] = __float2half_rn(gW1[j * 32 + (tid - 128)]);
        }
    }
    if (tid < 16) {    // W3T: [n][k] fp16, rows 10..15 zero
        __half* r = (__half*)(smc + W3T_BYTE + tid * 272);
        for (int k = 0; k < 136; ++k) r[k] = __float2half_rn(0.0f);
        if (tid < 10)
            for (int k = 0; k < 128; ++k) r[k] = __float2half_rn(dW3[k * 10 + tid]);
    }
    if (tid < 128) {
        ((float*)(smc + WT_BYTE))[tid]  = dW1[106 * 128 + tid];
        ((float*)(smc + DB2_BYTE))[tid] = db2[tid];
    }
    if (tid < 32) {
        ((float*)(smc + GWT_BYTE))[tid] = gW1[10 * 32 + tid];
        ((float*)(smc + GB1_BYTE))[tid] = gb1[tid];
    }
    if (tid < 16) {
        ((float*)(smc + GB2_BYTE))[tid] = (tid < 10) ? gb2[tid] : 0.0f;
        ((float*)(smc + DB3_BYTE))[tid] = (tid < 10) ? db3[tid] : 0.0f;
    }
    for (int i = tid; i <= nstep && i < 128; i += TPB)
        ((float*)(smc + TS_BYTE))[i] = ts[i];

    // ---- context encoders -> C[128] scattered into CF fragment layout ----
    if (tid < EPC) {
        const int elemE = blockIdx.x * EPC + tid;
        if (elemE < Bn) {
            float actv[6], rsv[3];
            #pragma unroll
            for (int j = 0; j < 6; ++j) actv[j] = activity[elemE * 6 + j];
            #pragma unroll
            for (int j = 0; j < 3; ++j) rsv[j] = rest[elemE * 3 + j];
            float ha[32];
            #pragma unroll
            for (int o = 0; o < 32; ++o) {
                float q = __ldg(&ab1[o]);
                #pragma unroll
                for (int j = 0; j < 6; ++j) q += actv[j] * __ldg(&aW1[j * 32 + o]);
                ha[o] = fmaxf(q, 0.0f);
            }
            float av[64];
            #pragma unroll
            for (int o = 0; o < 64; ++o) {
                float q = __ldg(&ab2[o]);
                #pragma unroll
                for (int j = 0; j < 32; ++j) q += ha[j] * __ldg(&aW2[j * 64 + o]);
                av[o] = q;
            }
            float hr[16];
            #pragma unroll
            for (int o = 0; o < 16; ++o) {
                float q = __ldg(&rb1[o]);
                #pragma unroll
                for (int j = 0; j < 3; ++j) q += rsv[j] * __ldg(&rW1[j * 16 + o]);
                hr[o] = fmaxf(q, 0.0f);
            }
            float rv[32];
            #pragma unroll
            for (int o = 0; o < 32; ++o) {
                float q = __ldg(&rb2[o]);
                #pragma unroll
                for (int j = 0; j < 16; ++j) q += hr[j] * __ldg(&rW2[j * 32 + o]);
                rv[o] = q;
            }
            const int w = tid >> 4, r = tid & 15;
            const uint32_t cfw = sbase + CF_BYTE + (uint32_t)w * 8192u;
            const int laneb = (r & 7) << 2;
            const int inner = (r >= 8) ? 8 : 0;
            for (int o4 = 0; o4 < 32; ++o4) {
                float cv[4];
                #pragma unroll
                for (int c = 0; c < 4; ++c) {
                    int o = o4 * 4 + c;
                    float q = __ldg(&db1[o]);
                    #pragma unroll
                    for (int j = 0; j < 64; ++j) q += av[j] * __ldg(&dW1[(10 + j) * 128 + o]);
                    #pragma unroll
                    for (int j = 0; j < 32; ++j) q += rv[j] * __ldg(&dW1[(74 + j) * 128 + o]);
                    cv[c] = q;
                }
                const int nt = o4 >> 1;
                const int t4b = 2 * (o4 & 1);
                uint32_t a0 = cfw + (uint32_t)((nt * 32 + laneb + t4b) * 16 + inner);
                uint32_t a1a = cfw + (uint32_t)((nt * 32 + laneb + t4b + 1) * 16 + inner);
                asm volatile("st.shared.v2.f32 [%0], {%1,%2};" :: "r"(a0), "f"(cv[0]), "f"(cv[1]));
                asm volatile("st.shared.v2.f32 [%0], {%1,%2};" :: "r"(a1a), "f"(cv[2]), "f"(cv[3]));
            }
        }
    }
    __syncthreads();
    if (!active) return;

    // ---- z state in fp32 fragment registers ----
    // zf0: cols qc,qc+1 rows gid (0,1) and gid+8 (2,3); zf1: cols 8+qc,9+qc
    float zf0[4], zf1[4];
    {
        const float* zb = z0 + (size_t)elemBase * 10;
        float2 a = *(const float2*)(zb + gid * 10 + qc);
        float2 b = *(const float2*)(zb + (gid + 8) * 10 + qc);
        zf0[0] = a.x; zf0[1] = a.y; zf0[2] = b.x; zf0[3] = b.y;
        zf1[0] = zf1[1] = zf1[2] = zf1[3] = 0.0f;
        if (tid4 == 0) {
            float2 c = *(const float2*)(zb + gid * 10 + 8);
            float2 d = *(const float2*)(zb + (gid + 8) * 10 + 8);
            zf1[0] = c.x; zf1[1] = c.y; zf1[2] = d.x; zf1[3] = d.y;
        }
        float* ob = out + (size_t)elemBase * 10;
        *(float2*)(ob + gid * 10 + qc)       = make_float2(zf0[0], zf0[1]);
        *(float2*)(ob + (gid + 8) * 10 + qc) = make_float2(zf0[2], zf0[3]);
        if (tid4 == 0) {
            *(float2*)(ob + gid * 10 + 8)       = make_float2(zf1[0], zf1[1]);
            *(float2*)(ob + (gid + 8) * 10 + 8) = make_float2(zf1[2], zf1[3]);
        }
    }

    // ---- gW2 B-fragments (registers, fixed) ----
    uint32_t gB[2][2][2];
    #pragma unroll
    for (int kt = 0; kt < 2; ++kt)
        #pragma unroll
        for (int nt = 0; nt < 2; ++nt) {
            const int n = nt * 8 + gid;
            float w00 = 0.f, w01 = 0.f, w10 = 0.f, w11 = 0.f;
            if (n < 10) {
                w00 = gW2[(16 * kt + 2 * tid4)     * 10 + n];
                w01 = gW2[(16 * kt + 2 * tid4 + 1) * 10 + n];
                w10 = gW2[(16 * kt + 2 * tid4 + 8) * 10 + n];
                w11 = gW2[(16 * kt + 2 * tid4 + 9) * 10 + n];
            }
            gB[kt][nt][0] = f16x2_of(w00, w01);
            gB[kt][nt][1] = f16x2_of(w10, w11);
        }
    float d3r[4], ga[4];
    {
        const float* d3 = (const float*)(smc + DB3_BYTE);
        const float* g2 = (const float*)(smc + GB2_BYTE);
        d3r[0] = d3[qc]; d3r[1] = d3[qc + 1]; d3r[2] = d3[8 + qc]; d3r[3] = d3[9 + qc];
        ga[0]  = g2[qc]; ga[1]  = g2[qc + 1]; ga[2]  = g2[8 + qc]; ga[3]  = g2[9 + qc];
    }

    // precomputed addresses
    const uint32_t w1L   = sbase + W1EXT_BYTE + (uint32_t)(lane & 7) * 48u
                         + (((uint32_t)lane >> 3) & 1u) * 16u + ((uint32_t)lane >> 4) * 384u;
    const uint32_t w3tL  = sbase + W3T_BYTE + (uint32_t)(lane & 7) * 272u
                         + ((uint32_t)lane >> 3) * 16u;
    const uint32_t bLdmLane = (uint32_t)(lane & 7) * 272u + ((uint32_t)lane >> 3) * 16u;
    const uint32_t cfW   = sbase + CF_BYTE + (uint32_t)wid * 8192u + (uint32_t)lane * 16u;
    const float* tsf = (const float*)(smc + TS_BYTE);

    // ================= SDE integration (fully register-resident state) =================
    for (int s = 0; s < nstep; ++s) {
        const float t  = tsf[s];
        const float dt = tsf[s + 1] - t;
        const float sq = sqrtf(dt);

        // ---- prefetch noise fragments (consumed at step end) ----
        const float* nb = noise + ((size_t)s * Bn + elemBase) * 10;
        float2 e00 = *(const float2*)(nb + gid * 10 + qc);
        float2 e01 = *(const float2*)(nb + (gid + 8) * 10 + qc);
        float2 e10 = make_float2(0.f, 0.f), e11 = make_float2(0.f, 0.f);
        if (tid4 == 0) {
            e10 = *(const float2*)(nb + gid * 10 + 8);
            e11 = *(const float2*)(nb + (gid + 8) * 10 + 8);
        }

        // ---- za A-fragments directly from state registers ----
        uint32_t za[4];
        za[0] = f16x2_of(zf0[0], zf0[1]);
        za[1] = f16x2_of(zf0[2], zf0[3]);
        za[2] = f16x2_of(zf1[0], zf1[1]);
        za[3] = f16x2_of(zf1[2], zf1[3]);

        // ---- GEMM1 drift: h1 = tanh(z@W1 + C + t*wt), two n-halves ----
        uint32_t af[8][4];
        #pragma unroll
        for (int hd = 0; hd < 2; ++hd) {
            float a1[8][4];
            #pragma unroll
            for (int nt = 0; nt < 8; ++nt) {
                const int gnt = 8 * hd + nt;
                float4 cf;
                asm volatile("ld.shared.v4.f32 {%0,%1,%2,%3}, [%4];"
                    : "=f"(cf.x), "=f"(cf.y), "=f"(cf.z), "=f"(cf.w)
                    : "r"(cfW + (uint32_t)gnt * 512u));
                float2 w2 = *(const float2*)(smc + WT_BYTE + (gnt * 8 + qc) * 4);
                a1[nt][0] = fmaf(t, w2.x, cf.x);
                a1[nt][1] = fmaf(t, w2.y, cf.y);
                a1[nt][2] = fmaf(t, w2.x, cf.z);
                a1[nt][3] = fmaf(t, w2.y, cf.w);
            }
            #pragma unroll
            for (int i = 0; i < 4; ++i) {
                uint32_t bw[4];
                ldm_x4(bw, w1L + (uint32_t)(8 * hd + 2 * i) * 384u);
                mma_f16(a1[2 * i],     za, bw[0], bw[1]);
                mma_f16(a1[2 * i + 1], za, bw[2], bw[3]);
            }
            #pragma unroll
            for (int kt = 0; kt < 4; ++kt) {
                af[4 * hd + kt][0] = tanh2(f16x2_of(a1[2 * kt][0],     a1[2 * kt][1]));
                af[4 * hd + kt][1] = tanh2(f16x2_of(a1[2 * kt][2],     a1[2 * kt][3]));
                af[4 * hd + kt][2] = tanh2(f16x2_of(a1[2 * kt + 1][0], a1[2 * kt + 1][1]));
                af[4 * hd + kt][3] = tanh2(f16x2_of(a1[2 * kt + 1][2], a1[2 * kt + 1][3]));
            }
        }

        // ---- diffusion layer 1 via GEMM1 extension + softplus + GEMM-g ----
        float accg[2][4];
        {
            float ag[4][4];
            const float* gb1f = (const float*)(smc + GB1_BYTE);
            const float* gwtf = (const float*)(smc + GWT_BYTE);
            #pragma unroll
            for (int nt = 0; nt < 4; ++nt) {
                const int c0 = nt * 8 + qc;
                float b0 = fmaf(t, gwtf[c0],     gb1f[c0]);
                float b1 = fmaf(t, gwtf[c0 + 1], gb1f[c0 + 1]);
                ag[nt][0] = b0; ag[nt][1] = b1; ag[nt][2] = b0; ag[nt][3] = b1;
            }
            #pragma unroll
            for (int i = 0; i < 2; ++i) {
                uint32_t bw[4];
                ldm_x4(bw, w1L + (uint32_t)(128 + 16 * i) * 48u);
                mma_f16(ag[2 * i],     za, bw[0], bw[1]);
                mma_f16(ag[2 * i + 1], za, bw[2], bw[3]);
            }
            uint32_t qf[2][4];
            #pragma unroll
            for (int kt = 0; kt < 2; ++kt) {
                qf[kt][0] = f16x2_of(softplus_(ag[2 * kt][0]),     softplus_(ag[2 * kt][1]));
                qf[kt][1] = f16x2_of(softplus_(ag[2 * kt][2]),     softplus_(ag[2 * kt][3]));
                qf[kt][2] = f16x2_of(softplus_(ag[2 * kt + 1][0]), softplus_(ag[2 * kt + 1][1]));
                qf[kt][3] = f16x2_of(softplus_(ag[2 * kt + 1][2]), softplus_(ag[2 * kt + 1][3]));
            }
            accg[0][0] = ga[0]; accg[0][1] = ga[1]; accg[0][2] = ga[0]; accg[0][3] = ga[1];
            accg[1][0] = ga[2]; accg[1][1] = ga[3]; accg[1][2] = ga[2]; accg[1][3] = ga[3];
            #pragma unroll
            for (int kt = 0; kt < 2; ++kt) {
                mma_f16(accg[0], qf[kt], gB[kt][0][0], gB[kt][0][1]);
                mma_f16(accg[1], qf[kt], gB[kt][1][0], gB[kt][1][1]);
            }
        }

        // ---- GEMM2 (h2) fused with GEMM3 (dz) ----
        float acc3[2][4];
        acc3[0][0] = d3r[0]; acc3[0][1] = d3r[1]; acc3[0][2] = d3r[0]; acc3[0][3] = d3r[1];
        acc3[1][0] = d3r[2]; acc3[1][1] = d3r[3]; acc3[1][2] = d3r[2]; acc3[1][3] = d3r[3];
        #pragma unroll
        for (int ng = 0; ng < 4; ++ng) {
            float acc[4][4];
            #pragma unroll
            for (int ni = 0; ni < 4; ++ni) {
                float2 d2 = *(const float2*)(smc + DB2_BYTE + ((ng * 4 + ni) * 8 + qc) * 4);
                acc[ni][0] = d2.x; acc[ni][1] = d2.y;
                acc[ni][2] = d2.x; acc[ni][3] = d2.y;
            }
            #pragma unroll
            for (int ni = 0; ni < 4; ++ni) {
                const uint32_t brow = sbase + W2F_BYTE + bLdmLane
                                    + (uint32_t)((ng * 4 + ni) * 8) * 272u;
                #pragma unroll
                for (int ktp = 0; ktp < 4; ++ktp) {
                    uint32_t r[4];
                    ldm_x4(r, brow + (uint32_t)ktp * 64u);
                    mma_f16(acc[ni], af[2 * ktp],     r[0], r[1]);
                    mma_f16(acc[ni], af[2 * ktp + 1], r[2], r[3]);
                }
            }
            uint32_t r3a[4], r3b[4];
            ldm_x4(r3a, w3tL + (uint32_t)ng * 64u);
            ldm_x4(r3b, w3tL + 8 * 272u + (uint32_t)ng * 64u);
            #pragma unroll
            for (int p = 0; p < 2; ++p) {
                uint32_t a3[4];
                a3[0] = tanh2(f16x2_of(acc[2 * p][0],     acc[2 * p][1]));
                a3[1] = tanh2(f16x2_of(acc[2 * p][2],     acc[2 * p][3]));
                a3[2] = tanh2(f16x2_of(acc[2 * p + 1][0], acc[2 * p + 1][1]));
                a3[3] = tanh2(f16x2_of(acc[2 * p + 1][2], acc[2 * p + 1][3]));
                mma_f16(acc3[0], a3, r3a[2 * p], r3a[2 * p + 1]);
                mma_f16(acc3[1], a3, r3b[2 * p], r3b[2 * p + 1]);
            }
        }

        // ---- Euler-Maruyama update in fragment space + fragment store ----
        zf0[0] += acc3[0][0] * dt + accg[0][0] * sq * e00.x;
        zf0[1] += acc3[0][1] * dt + accg[0][1] * sq * e00.y;
        zf0[2] += acc3[0][2] * dt + accg[0][2] * sq * e01.x;
        zf0[3] += acc3[0][3] * dt + accg[0][3] * sq * e01.y;
        zf1[0] += acc3[1][0] * dt + accg[1][0] * sq * e10.x;
        zf1[1] += acc3[1][1] * dt + accg[1][1] * sq * e10.y;
        zf1[2] += acc3[1][2] * dt + accg[1][2] * sq * e11.x;
        zf1[3] += acc3[1][3] * dt + accg[1][3] * sq * e11.y;

        float* ob = out + ((size_t)(s + 1) * Bn + elemBase) * 10;
        *(float2*)(ob + gid * 10 + qc)       = make_float2(zf0[0], zf0[1]);
        *(float2*)(ob + (gid + 8) * 10 + qc) = make_float2(zf0[2], zf0[3]);
        if (tid4 == 0) {
            *(float2*)(ob + gid * 10 + 8)       = make_float2(zf1[0], zf1[1]);
            *(float2*)(ob + (gid + 8) * 10 + 8) = make_float2(zf1[2], zf1[3]);
        }
    }
}

extern "C" void kernel_launch(void* const* d_in, const int* in_sizes, int n_in,
                              void* d_out, int out_size) {
    const float* z0       = (const float*)d_in[0];
    const float* activity = (const float*)d_in[1];
    const float* rest     = (const float*)d_in[2];
    const float* ts       = (const float*)d_in[3];
    const float* noise    = (const float*)d_in[4];
    const float* aW1 = (const float*)d_in[5];
    const float* ab1 = (const float*)d_in[6];
    const float* aW2 = (const float*)d_in[7];
    const float* ab2 = (const float*)d_in[8];
    const float* rW1 = (const float*)d_in[9];
    const float* rb1 = (const float*)d_in[10];
    const float* rW2 = (const float*)d_in[11];
    const float* rb2 = (const float*)d_in[12];
    const float* dW1 = (const float*)d_in[13];
    const float* db1 = (const float*)d_in[14];
    const float* dW2 = (const float*)d_in[15];
    const float* db2 = (const float*)d_in[16];
    const float* dW3 = (const float*)d_in[17];
    const float* db3 = (const float*)d_in[18];
    const float* gW1 = (const float*)d_in[19];
    const float* gb1 = (const float*)d_in[20];
    const float* gW2 = (const float*)d_in[21];
    const float* gb2 = (const float*)d_in[22];

    int B     = in_sizes[0] / 10;
    int nstep = in_sizes[3] - 1;

    cudaFuncSetAttribute(sde_hmma, cudaFuncAttributeMaxDynamicSharedMemorySize,
                         SMEM_BYTES);
    int grid = (B + EPC - 1) / EPC;
    sde_hmma<<<grid, TPB, SMEM_BYTES>>>(
        z0, activity, rest, ts, noise,
        aW1, ab1, aW2, ab2, rW1, rb1, rW2, rb2,
        dW1, db1, dW2, db2, dW3, db3,
        gW1, gb1, gW2, gb2,
        (float*)d_out, B, nstep);
}

// round 16
// speedup vs baseline: 1.9387x; 1.0704x over previous
#include <cuda_runtime.h>
#include <cuda_bf16.h>
#include <cuda_fp16.h>
#include <cstdint>
#include <cstddef>

#define TPB 224
#define NWARP 7
#define EPC 224          // elements per CTA (7 warps x 32)

// ---------------- helpers ----------------
__device__ __forceinline__ uint32_t f16x2_of(float lo, float hi) {
    uint32_t r; asm("cvt.rn.f16x2.f32 %0, %1, %2;" : "=r"(r) : "f"(hi), "f"(lo)); return r;
}
__device__ __forceinline__ uint32_t tanh2(uint32_t x) {
    uint32_t y; asm("tanh.approx.f16x2 %0, %1;" : "=r"(y) : "r"(x)); return y;
}
__device__ __forceinline__ float softplus_(float x) {
    return fmaxf(x, 0.0f) + __logf(1.0f + __expf(-fabsf(x)));
}
__device__ __forceinline__ void mma_f16(float* c, const uint32_t* a, uint32_t b0, uint32_t b1) {
    asm volatile("mma.sync.aligned.m16n8k16.row.col.f32.f16.f16.f32 "
        "{%0,%1,%2,%3}, {%4,%5,%6,%7}, {%8,%9}, {%0,%1,%2,%3};"
        : "+f"(c[0]), "+f"(c[1]), "+f"(c[2]), "+f"(c[3])
        : "r"(a[0]), "r"(a[1]), "r"(a[2]), "r"(a[3]), "r"(b0), "r"(b1));
}
__device__ __forceinline__ void ldm_x4(uint32_t* r, uint32_t addr) {
    asm volatile("ldmatrix.sync.aligned.m8n8.x4.shared.b16 {%0,%1,%2,%3}, [%4];"
        : "=r"(r[0]), "=r"(r[1]), "=r"(r[2]), "=r"(r[3]) : "r"(addr));
}
__device__ __forceinline__ uint32_t smem_u32(const void* p) {
    uint32_t a;
    asm("{ .reg .u64 t; cvta.to.shared.u64 t, %1; cvt.u32.u64 %0, t; }" : "=r"(a) : "l"(p));
    return a;
}

// ---------------- SMEM byte layout ----------------
#define W1EXT_BYTE  0                        // 160 n-rows x 48B fp16 (k16: W1|gW1 cols)
#define W3T_BYTE    7680                     // 16 n-rows x 272B fp16 (k128)  [dW3^T]
#define CF_BYTE     12032                    // 14 tiles x 16nt x 32 lanes x 16B (C frags)
#define W2F_BYTE    126720                   // W2^T fp16: 128 x 272B
#define DB2_BYTE    161536                   // 128 f
#define WT_BYTE     162048                   // 128 f (t-row of dW1)
#define GWT_BYTE    162560                   // 32 f (t-row of gW1)
#define GB1_BYTE    162688                   // 32 f
#define GB2_BYTE    162816                   // 16 f (pad 0)
#define DB3_BYTE    162880                   // 16 f (pad 0)
#define TS_BYTE     162944                   // 128 f
#define SMEM_BYTES  163456

__global__ void __launch_bounds__(TPB, 1)
sde_hmma(const float* __restrict__ z0, const float* __restrict__ activity,
         const float* __restrict__ rest, const float* __restrict__ ts,
         const float* __restrict__ noise,
         const float* __restrict__ aW1, const float* __restrict__ ab1,
         const float* __restrict__ aW2, const float* __restrict__ ab2,
         const float* __restrict__ rW1, const float* __restrict__ rb1,
         const float* __restrict__ rW2, const float* __restrict__ rb2,
         const float* __restrict__ dW1, const float* __restrict__ db1,
         const float* __restrict__ dW2, const float* __restrict__ db2,
         const float* __restrict__ dW3, const float* __restrict__ db3,
         const float* __restrict__ gW1, const float* __restrict__ gb1,
         const float* __restrict__ gW2, const float* __restrict__ gb2,
         float* __restrict__ out, int Bn, int nstep)
{
    extern __shared__ char smc[];
    const uint32_t sbase = smem_u32(smc);
    const int tid  = threadIdx.x;
    const int wid  = tid >> 5;
    const int lane = tid & 31;
    const int gid  = lane >> 2;
    const int tid4 = lane & 3;
    const int qc   = tid4 * 2;
    const int elemBase = blockIdx.x * EPC + wid * 32;   // warp owns 32 elems, 2 tiles
    const bool active  = (elemBase < Bn);

    // ================= one-time staging =================
    for (int i = tid; i < 16384; i += TPB) {
        int k = i >> 7, n = i & 127;
        *(__half*)(smc + W2F_BYTE + (uint32_t)n * 272u + (uint32_t)k * 2u) =
            __float2half_rn(dW2[i]);
    }
    if (tid < 160) {   // W1EXT rows: 0..127 drift, 128..159 diffusion
        __half* r = (__half*)(smc + W1EXT_BYTE + tid * 48);
        #pragma unroll
        for (int k = 0; k < 24; ++k) r[k] = __float2half_rn(0.0f);
        if (tid < 128) {
            #pragma unroll
            for (int j = 0; j < 10; ++j) r[j] = __float2half_rn(dW1[j * 128 + tid]);
        } else {
            #pragma unroll
            for (int j = 0; j < 10; ++j) r[j] = __float2half_rn(gW1[j * 32 + (tid - 128)]);
        }
    }
    if (tid < 16) {    // W3T: [n][k] fp16, rows 10..15 zero
        __half* r = (__half*)(smc + W3T_BYTE + tid * 272);
        for (int k = 0; k < 136; ++k) r[k] = __float2half_rn(0.0f);
        if (tid < 10)
            for (int k = 0; k < 128; ++k) r[k] = __float2half_rn(dW3[k * 10 + tid]);
    }
    if (tid < 128) {
        ((float*)(smc + WT_BYTE))[tid]  = dW1[106 * 128 + tid];
        ((float*)(smc + DB2_BYTE))[tid] = db2[tid];
    }
    if (tid < 32) {
        ((float*)(smc + GWT_BYTE))[tid] = gW1[10 * 32 + tid];
        ((float*)(smc + GB1_BYTE))[tid] = gb1[tid];
    }
    if (tid < 16) {
        ((float*)(smc + GB2_BYTE))[tid] = (tid < 10) ? gb2[tid] : 0.0f;
        ((float*)(smc + DB3_BYTE))[tid] = (tid < 10) ? db3[tid] : 0.0f;
    }
    for (int i = tid; i <= nstep && i < 128; i += TPB)
        ((float*)(smc + TS_BYTE))[i] = ts[i];

    // ---- context encoders -> C[128] scattered into CF fragment layout ----
    if (tid < EPC) {
        const int elemE = blockIdx.x * EPC + tid;
        if (elemE < Bn) {
            float actv[6], rsv[3];
            #pragma unroll
            for (int j = 0; j < 6; ++j) actv[j] = activity[elemE * 6 + j];
            #pragma unroll
            for (int j = 0; j < 3; ++j) rsv[j] = rest[elemE * 3 + j];
            float ha[32];
            #pragma unroll
            for (int o = 0; o < 32; ++o) {
                float q = __ldg(&ab1[o]);
                #pragma unroll
                for (int j = 0; j < 6; ++j) q += actv[j] * __ldg(&aW1[j * 32 + o]);
                ha[o] = fmaxf(q, 0.0f);
            }
            float av[64];
            #pragma unroll
            for (int o = 0; o < 64; ++o) {
                float q = __ldg(&ab2[o]);
                #pragma unroll
                for (int j = 0; j < 32; ++j) q += ha[j] * __ldg(&aW2[j * 64 + o]);
                av[o] = q;
            }
            float hr[16];
            #pragma unroll
            for (int o = 0; o < 16; ++o) {
                float q = __ldg(&rb1[o]);
                #pragma unroll
                for (int j = 0; j < 3; ++j) q += rsv[j] * __ldg(&rW1[j * 16 + o]);
                hr[o] = fmaxf(q, 0.0f);
            }
            float rv[32];
            #pragma unroll
            for (int o = 0; o < 32; ++o) {
                float q = __ldg(&rb2[o]);
                #pragma unroll
                for (int j = 0; j < 16; ++j) q += hr[j] * __ldg(&rW2[j * 32 + o]);
                rv[o] = q;
            }
            // tile index: warp (tid>>5), tile within warp ((tid>>4)&1)
            const int w = tid >> 5, mt = (tid >> 4) & 1, r = tid & 15;
            const uint32_t cfw = sbase + CF_BYTE + (uint32_t)(w * 2 + mt) * 8192u;
            const int laneb = (r & 7) << 2;
            const int inner = (r >= 8) ? 8 : 0;
            for (int o4 = 0; o4 < 32; ++o4) {
                float cv[4];
                #pragma unroll
                for (int c = 0; c < 4; ++c) {
                    int o = o4 * 4 + c;
                    float q = __ldg(&db1[o]);
                    #pragma unroll
                    for (int j = 0; j < 64; ++j) q += av[j] * __ldg(&dW1[(10 + j) * 128 + o]);
                    #pragma unroll
                    for (int j = 0; j < 32; ++j) q += rv[j] * __ldg(&dW1[(74 + j) * 128 + o]);
                    cv[c] = q;
                }
                const int nt = o4 >> 1;
                const int t4b = 2 * (o4 & 1);
                uint32_t a0 = cfw + (uint32_t)((nt * 32 + laneb + t4b) * 16 + inner);
                uint32_t a1a = cfw + (uint32_t)((nt * 32 + laneb + t4b + 1) * 16 + inner);
                asm volatile("st.shared.v2.f32 [%0], {%1,%2};" :: "r"(a0), "f"(cv[0]), "f"(cv[1]));
                asm volatile("st.shared.v2.f32 [%0], {%1,%2};" :: "r"(a1a), "f"(cv[2]), "f"(cv[3]));
            }
        }
    }
    __syncthreads();
    if (!active) return;

    // ---- z state in fp32 fragment registers, 2 tiles ----
    float zf0[2][4], zf1[2][4];
    #pragma unroll
    for (int mt = 0; mt < 2; ++mt) {
        const float* zb = z0 + (size_t)(elemBase + mt * 16) * 10;
        float2 a = *(const float2*)(zb + gid * 10 + qc);
        float2 b = *(const float2*)(zb + (gid + 8) * 10 + qc);
        zf0[mt][0] = a.x; zf0[mt][1] = a.y; zf0[mt][2] = b.x; zf0[mt][3] = b.y;
        zf1[mt][0] = zf1[mt][1] = zf1[mt][2] = zf1[mt][3] = 0.0f;
        if (tid4 == 0) {
            float2 c = *(const float2*)(zb + gid * 10 + 8);
            float2 d = *(const float2*)(zb + (gid + 8) * 10 + 8);
            zf1[mt][0] = c.x; zf1[mt][1] = c.y; zf1[mt][2] = d.x; zf1[mt][3] = d.y;
        }
        float* ob = out + (size_t)(elemBase + mt * 16) * 10;
        *(float2*)(ob + gid * 10 + qc)       = make_float2(zf0[mt][0], zf0[mt][1]);
        *(float2*)(ob + (gid + 8) * 10 + qc) = make_float2(zf0[mt][2], zf0[mt][3]);
        if (tid4 == 0) {
            *(float2*)(ob + gid * 10 + 8)       = make_float2(zf1[mt][0], zf1[mt][1]);
            *(float2*)(ob + (gid + 8) * 10 + 8) = make_float2(zf1[mt][2], zf1[mt][3]);
        }
    }

    // ---- gW2 B-fragments (registers, fixed) ----
    uint32_t gB[2][2][2];
    #pragma unroll
    for (int kt = 0; kt < 2; ++kt)
        #pragma unroll
        for (int nt = 0; nt < 2; ++nt) {
            const int n = nt * 8 + gid;
            float w00 = 0.f, w01 = 0.f, w10 = 0.f, w11 = 0.f;
            if (n < 10) {
                w00 = gW2[(16 * kt + 2 * tid4)     * 10 + n];
                w01 = gW2[(16 * kt + 2 * tid4 + 1) * 10 + n];
                w10 = gW2[(16 * kt + 2 * tid4 + 8) * 10 + n];
                w11 = gW2[(16 * kt + 2 * tid4 + 9) * 10 + n];
            }
            gB[kt][nt][0] = f16x2_of(w00, w01);
            gB[kt][nt][1] = f16x2_of(w10, w11);
        }
    float d3r[4], ga[4];
    {
        const float* d3 = (const float*)(smc + DB3_BYTE);
        const float* g2 = (const float*)(smc + GB2_BYTE);
        d3r[0] = d3[qc]; d3r[1] = d3[qc + 1]; d3r[2] = d3[8 + qc]; d3r[3] = d3[9 + qc];
        ga[0]  = g2[qc]; ga[1]  = g2[qc + 1]; ga[2]  = g2[8 + qc]; ga[3]  = g2[9 + qc];
    }

    // precomputed addresses
    const uint32_t w1L   = sbase + W1EXT_BYTE + (uint32_t)(lane & 7) * 48u
                         + (((uint32_t)lane >> 3) & 1u) * 16u + ((uint32_t)lane >> 4) * 384u;
    const uint32_t w3tL  = sbase + W3T_BYTE + (uint32_t)(lane & 7) * 272u
                         + ((uint32_t)lane >> 3) * 16u;
    const uint32_t bLdmLane = (uint32_t)(lane & 7) * 272u + ((uint32_t)lane >> 3) * 16u;
    const uint32_t cfW   = sbase + CF_BYTE + (uint32_t)(wid * 2) * 8192u + (uint32_t)lane * 16u;
    const float* tsf = (const float*)(smc + TS_BYTE);

    // ================= SDE integration (2 M-tiles per warp, reg-resident) =================
    for (int s = 0; s < nstep; ++s) {
        const float t  = tsf[s];
        const float dt = tsf[s + 1] - t;
        const float sq = sqrtf(dt);

        // ---- prefetch noise fragments for both tiles ----
        float2 e00[2], e01[2], e10[2], e11[2];
        #pragma unroll
        for (int mt = 0; mt < 2; ++mt) {
            const float* nb = noise + ((size_t)s * Bn + elemBase + mt * 16) * 10;
            e00[mt] = *(const float2*)(nb + gid * 10 + qc);
            e01[mt] = *(const float2*)(nb + (gid + 8) * 10 + qc);
            e10[mt] = make_float2(0.f, 0.f); e11[mt] = make_float2(0.f, 0.f);
            if (tid4 == 0) {
                e10[mt] = *(const float2*)(nb + gid * 10 + 8);
                e11[mt] = *(const float2*)(nb + (gid + 8) * 10 + 8);
            }
        }

        // ---- za A-fragments from state registers ----
        uint32_t za[2][4];
        #pragma unroll
        for (int mt = 0; mt < 2; ++mt) {
            za[mt][0] = f16x2_of(zf0[mt][0], zf0[mt][1]);
            za[mt][1] = f16x2_of(zf0[mt][2], zf0[mt][3]);
            za[mt][2] = f16x2_of(zf1[mt][0], zf1[mt][1]);
            za[mt][3] = f16x2_of(zf1[mt][2], zf1[mt][3]);
        }

        // ---- GEMM1 drift: shared B-ldm, both tiles ----
        uint32_t af[2][8][4];
        #pragma unroll
        for (int hd = 0; hd < 2; ++hd) {
            float a1[2][8][4];
            #pragma unroll
            for (int nt = 0; nt < 8; ++nt) {
                const int gnt = 8 * hd + nt;
                float2 w2 = *(const float2*)(smc + WT_BYTE + (gnt * 8 + qc) * 4);
                #pragma unroll
                for (int mt = 0; mt < 2; ++mt) {
                    float4 cf;
                    asm volatile("ld.shared.v4.f32 {%0,%1,%2,%3}, [%4];"
                        : "=f"(cf.x), "=f"(cf.y), "=f"(cf.z), "=f"(cf.w)
                        : "r"(cfW + (uint32_t)mt * 8192u + (uint32_t)gnt * 512u));
                    a1[mt][nt][0] = fmaf(t, w2.x, cf.x);
                    a1[mt][nt][1] = fmaf(t, w2.y, cf.y);
                    a1[mt][nt][2] = fmaf(t, w2.x, cf.z);
                    a1[mt][nt][3] = fmaf(t, w2.y, cf.w);
                }
            }
            #pragma unroll
            for (int i = 0; i < 4; ++i) {
                uint32_t bw[4];
                ldm_x4(bw, w1L + (uint32_t)(8 * hd + 2 * i) * 384u);
                #pragma unroll
                for (int mt = 0; mt < 2; ++mt) {
                    mma_f16(a1[mt][2 * i],     za[mt], bw[0], bw[1]);
                    mma_f16(a1[mt][2 * i + 1], za[mt], bw[2], bw[3]);
                }
            }
            #pragma unroll
            for (int kt = 0; kt < 4; ++kt)
                #pragma unroll
                for (int mt = 0; mt < 2; ++mt) {
                    af[mt][4 * hd + kt][0] = tanh2(f16x2_of(a1[mt][2 * kt][0],     a1[mt][2 * kt][1]));
                    af[mt][4 * hd + kt][1] = tanh2(f16x2_of(a1[mt][2 * kt][2],     a1[mt][2 * kt][3]));
                    af[mt][4 * hd + kt][2] = tanh2(f16x2_of(a1[mt][2 * kt + 1][0], a1[mt][2 * kt + 1][1]));
                    af[mt][4 * hd + kt][3] = tanh2(f16x2_of(a1[mt][2 * kt + 1][2], a1[mt][2 * kt + 1][3]));
                }
        }

        // ---- diffusion: GEMM-ext + softplus + GEMM-g; fold g-term into zf now ----
        {
            float ag[2][4][4];
            const float* gb1f = (const float*)(smc + GB1_BYTE);
            const float* gwtf = (const float*)(smc + GWT_BYTE);
            #pragma unroll
            for (int nt = 0; nt < 4; ++nt) {
                const int c0 = nt * 8 + qc;
                float b0 = fmaf(t, gwtf[c0],     gb1f[c0]);
                float b1 = fmaf(t, gwtf[c0 + 1], gb1f[c0 + 1]);
                #pragma unroll
                for (int mt = 0; mt < 2; ++mt) {
                    ag[mt][nt][0] = b0; ag[mt][nt][1] = b1;
                    ag[mt][nt][2] = b0; ag[mt][nt][3] = b1;
                }
            }
            #pragma unroll
            for (int i = 0; i < 2; ++i) {
                uint32_t bw[4];
                ldm_x4(bw, w1L + (uint32_t)(128 + 16 * i) * 48u);
                #pragma unroll
                for (int mt = 0; mt < 2; ++mt) {
                    mma_f16(ag[mt][2 * i],     za[mt], bw[0], bw[1]);
                    mma_f16(ag[mt][2 * i + 1], za[mt], bw[2], bw[3]);
                }
            }
            #pragma unroll
            for (int mt = 0; mt < 2; ++mt) {
                uint32_t qf[2][4];
                #pragma unroll
                for (int kt = 0; kt < 2; ++kt) {
                    qf[kt][0] = f16x2_of(softplus_(ag[mt][2 * kt][0]),     softplus_(ag[mt][2 * kt][1]));
                    qf[kt][1] = f16x2_of(softplus_(ag[mt][2 * kt][2]),     softplus_(ag[mt][2 * kt][3]));
                    qf[kt][2] = f16x2_of(softplus_(ag[mt][2 * kt + 1][0]), softplus_(ag[mt][2 * kt + 1][1]));
                    qf[kt][3] = f16x2_of(softplus_(ag[mt][2 * kt + 1][2]), softplus_(ag[mt][2 * kt + 1][3]));
                }
                float accg[2][4];
                accg[0][0] = ga[0]; accg[0][1] = ga[1]; accg[0][2] = ga[0]; accg[0][3] = ga[1];
                accg[1][0] = ga[2]; accg[1][1] = ga[3]; accg[1][2] = ga[2]; accg[1][3] = ga[3];
                #pragma unroll
                for (int kt = 0; kt < 2; ++kt) {
                    mma_f16(accg[0], qf[kt], gB[kt][0][0], gB[kt][0][1]);
                    mma_f16(accg[1], qf[kt], gB[kt][1][0], gB[kt][1][1]);
                }
                // fold diffusion term into state now (EM update is additive)
                zf0[mt][0] += accg[0][0] * sq * e00[mt].x;
                zf0[mt][1] += accg[0][1] * sq * e00[mt].y;
                zf0[mt][2] += accg[0][2] * sq * e01[mt].x;
                zf0[mt][3] += accg[0][3] * sq * e01[mt].y;
                zf1[mt][0] += accg[1][0] * sq * e10[mt].x;
                zf1[mt][1] += accg[1][1] * sq * e10[mt].y;
                zf1[mt][2] += accg[1][2] * sq * e11[mt].x;
                zf1[mt][3] += accg[1][3] * sq * e11[mt].y;
            }
        }

        // ---- GEMM2 (h2) fused with GEMM3 (dz), shared B-ldm for both tiles ----
        float acc3[2][2][4];
        #pragma unroll
        for (int mt = 0; mt < 2; ++mt) {
            acc3[mt][0][0] = d3r[0]; acc3[mt][0][1] = d3r[1];
            acc3[mt][0][2] = d3r[0]; acc3[mt][0][3] = d3r[1];
            acc3[mt][1][0] = d3r[2]; acc3[mt][1][1] = d3r[3];
            acc3[mt][1][2] = d3r[2]; acc3[mt][1][3] = d3r[3];
        }
        #pragma unroll
        for (int ng = 0; ng < 4; ++ng) {
            float acc[2][4][4];
            #pragma unroll
            for (int ni = 0; ni < 4; ++ni) {
                float2 d2 = *(const float2*)(smc + DB2_BYTE + ((ng * 4 + ni) * 8 + qc) * 4);
                #pragma unroll
                for (int mt = 0; mt < 2; ++mt) {
                    acc[mt][ni][0] = d2.x; acc[mt][ni][1] = d2.y;
                    acc[mt][ni][2] = d2.x; acc[mt][ni][3] = d2.y;
                }
            }
            #pragma unroll
            for (int ni = 0; ni < 4; ++ni) {
                const uint32_t brow = sbase + W2F_BYTE + bLdmLane
                                    + (uint32_t)((ng * 4 + ni) * 8) * 272u;
                #pragma unroll
                for (int ktp = 0; ktp < 4; ++ktp) {
                    uint32_t r[4];
                    ldm_x4(r, brow + (uint32_t)ktp * 64u);
                    #pragma unroll
                    for (int mt = 0; mt < 2; ++mt) {
                        mma_f16(acc[mt][ni], af[mt][2 * ktp],     r[0], r[1]);
                        mma_f16(acc[mt][ni], af[mt][2 * ktp + 1], r[2], r[3]);
                    }
                }
            }
            uint32_t r3a[4], r3b[4];
            ldm_x4(r3a, w3tL + (uint32_t)ng * 64u);
            ldm_x4(r3b, w3tL + 8 * 272u + (uint32_t)ng * 64u);
            #pragma unroll
            for (int mt = 0; mt < 2; ++mt)
                #pragma unroll
                for (int p = 0; p < 2; ++p) {
                    uint32_t a3[4];
                    a3[0] = tanh2(f16x2_of(acc[mt][2 * p][0],     acc[mt][2 * p][1]));
                    a3[1] = tanh2(f16x2_of(acc[mt][2 * p][2],     acc[mt][2 * p][3]));
                    a3[2] = tanh2(f16x2_of(acc[mt][2 * p + 1][0], acc[mt][2 * p + 1][1]));
                    a3[3] = tanh2(f16x2_of(acc[mt][2 * p + 1][2], acc[mt][2 * p + 1][3]));
                    mma_f16(acc3[mt][0], a3, r3a[2 * p], r3a[2 * p + 1]);
                    mma_f16(acc3[mt][1], a3, r3b[2 * p], r3b[2 * p + 1]);
                }
        }

        // ---- drift term + store (g-term already folded) ----
        #pragma unroll
        for (int mt = 0; mt < 2; ++mt) {
            zf0[mt][0] += acc3[mt][0][0] * dt;
            zf0[mt][1] += acc3[mt][0][1] * dt;
            zf0[mt][2] += acc3[mt][0][2] * dt;
            zf0[mt][3] += acc3[mt][0][3] * dt;
            zf1[mt][0] += acc3[mt][1][0] * dt;
            zf1[mt][1] += acc3[mt][1][1] * dt;
            zf1[mt][2] += acc3[mt][1][2] * dt;
            zf1[mt][3] += acc3[mt][1][3] * dt;

            float* ob = out + ((size_t)(s + 1) * Bn + elemBase + mt * 16) * 10;
            *(float2*)(ob + gid * 10 + qc)       = make_float2(zf0[mt][0], zf0[mt][1]);
            *(float2*)(ob + (gid + 8) * 10 + qc) = make_float2(zf0[mt][2], zf0[mt][3]);
            if (tid4 == 0) {
                *(float2*)(ob + gid * 10 + 8)       = make_float2(zf1[mt][0], zf1[mt][1]);
                *(float2*)(ob + (gid + 8) * 10 + 8) = make_float2(zf1[mt][2], zf1[mt][3]);
            }
        }
    }
}

extern "C" void kernel_launch(void* const* d_in, const int* in_sizes, int n_in,
                              void* d_out, int out_size) {
    const float* z0       = (const float*)d_in[0];
    const float* activity = (const float*)d_in[1];
    const float* rest     = (const float*)d_in[2];
    const float* ts       = (const float*)d_in[3];
    const float* noise    = (const float*)d_in[4];
    const float* aW1 = (const float*)d_in[5];
    const float* ab1 = (const float*)d_in[6];
    const float* aW2 = (const float*)d_in[7];
    const float* ab2 = (const float*)d_in[8];
    const float* rW1 = (const float*)d_in[9];
    const float* rb1 = (const float*)d_in[10];
    const float* rW2 = (const float*)d_in[11];
    const float* rb2 = (const float*)d_in[12];
    const float* dW1 = (const float*)d_in[13];
    const float* db1 = (const float*)d_in[14];
    const float* dW2 = (const float*)d_in[15];
    const float* db2 = (const float*)d_in[16];
    const float* dW3 = (const float*)d_in[17];
    const float* db3 = (const float*)d_in[18];
    const float* gW1 = (const float*)d_in[19];
    const float* gb1 = (const float*)d_in[20];
    const float* gW2 = (const float*)d_in[21];
    const float* gb2 = (const float*)d_in[22];

    int B     = in_sizes[0] / 10;
    int nstep = in_sizes[3] - 1;

    cudaFuncSetAttribute(sde_hmma, cudaFuncAttributeMaxDynamicSharedMemorySize,
                         SMEM_BYTES);
    int grid = (B + EPC - 1) / EPC;
    sde_hmma<<<grid, TPB, SMEM_BYTES>>>(
        z0, activity, rest, ts, noise,
        aW1, ab1, aW2, ab2, rW1, rb1, rW2, rb2,
        dW1, db1, dW2, db2, dW3, db3,
        gW1, gb1, gW2, gb2,
        (float*)d_out, B, nstep);
}